// round 8
// baseline (speedup 1.0000x reference)
#include <cuda_runtime.h>
#include <cuda_fp16.h>
#include <cstdint>
#include <math.h>

// Problem constants (MoDRouter_48387101556956: fixed shapes)
#define BB   4
#define NN   4096
#define DD   1024
#define DFFN 4096
#define KK   2048
#define MM   (BB * KK)   // 8192 selected tokens total

// ---------------------------------------------------------------------------
// Device scratch
// ---------------------------------------------------------------------------
__device__ float  g_scores[BB * NN];
__device__ int    g_sel[MM];                       // selected token idx per (b,j)
__device__ __half g_a[(size_t)MM * DD];            // gathered + fp16 A (16 MB)
__device__ __half g_w1t[(size_t)DFFN * DD];        // w1^T (n-major, K contig), fp16
__device__ __half g_w2t[(size_t)DD * DFFN];        // w2^T (n-major, K contig), fp16
__device__ __half g_h[(size_t)MM * DFFN];          // gelu(x@w1+b1), fp16 (64 MB)

// ---------------------------------------------------------------------------
// Helpers
// ---------------------------------------------------------------------------
__device__ __forceinline__ uint32_t smem_u32(const void* p) {
    uint32_t a;
    asm("{ .reg .u64 t; cvta.to.shared.u64 t, %1; cvt.u32.u64 %0, t; }" : "=r"(a) : "l"(p));
    return a;
}
__device__ __forceinline__ float gelu_tanh(float u) {
    float t = tanhf(0.7978845608028654f * (u + 0.044715f * u * u * u));
    return 0.5f * u * (1.0f + t);
}

#define CP_ASYNC16(dst, src) \
    asm volatile("cp.async.cg.shared.global [%0], [%1], 16;" :: "r"(dst), "l"(src) : "memory")
#define CP_COMMIT() asm volatile("cp.async.commit_group;" ::: "memory")
#define CP_WAIT1()  asm volatile("cp.async.wait_group 1;" ::: "memory")

// m16n8k16 row.col fp16 MMA, fp32 accumulate (base-ISA, legal on sm_103)
#define MMA_F16(c, a, b0, b1)                                                         \
    asm volatile("mma.sync.aligned.m16n8k16.row.col.f32.f16.f16.f32 "                 \
                 "{%0,%1,%2,%3}, {%4,%5,%6,%7}, {%8,%9}, {%0,%1,%2,%3};"              \
                 : "+f"((c)[0]), "+f"((c)[1]), "+f"((c)[2]), "+f"((c)[3])             \
                 : "r"((a)[0]), "r"((a)[1]), "r"((a)[2]), "r"((a)[3]), "r"(b0), "r"(b1))

// ldmatrix 4x m8n8 b16 (non-transposed)
#define LDSM_X4(r0, r1, r2, r3, addr)                                                 \
    asm volatile("ldmatrix.sync.aligned.m8n8.x4.shared.b16 {%0,%1,%2,%3}, [%4];"      \
                 : "=r"(r0), "=r"(r1), "=r"(r2), "=r"(r3) : "r"(addr))

// ---------------------------------------------------------------------------
// 1) Gate scores + out=x copy fused — one warp per row (reads the row anyway)
// ---------------------------------------------------------------------------
__global__ void scores_copy_kernel(const float* __restrict__ x,
                                   const float* __restrict__ gw,
                                   float* __restrict__ out) {
    int gwarp = (blockIdx.x * blockDim.x + threadIdx.x) >> 5;
    int lane  = threadIdx.x & 31;
    if (gwarp >= BB * NN) return;
    const float4* xr = reinterpret_cast<const float4*>(x + (size_t)gwarp * DD);
    float4*       orow = reinterpret_cast<float4*>(out + (size_t)gwarp * DD);
    const float4* g4 = reinterpret_cast<const float4*>(gw);
    float s = 0.0f;
#pragma unroll
    for (int i = 0; i < DD / 4 / 32; ++i) {
        float4 a = xr[lane + i * 32];
        float4 b = g4[lane + i * 32];
        orow[lane + i * 32] = a;                      // fused copy
        s += a.x * b.x + a.y * b.y + a.z * b.z + a.w * b.w;
    }
#pragma unroll
    for (int o = 16; o; o >>= 1) s += __shfl_xor_sync(0xFFFFFFFFu, s, o);
    if (lane == 0) g_scores[gwarp] = s;
}

// ---------------------------------------------------------------------------
// 2) Per-batch top-K via bitonic sort
// ---------------------------------------------------------------------------
__global__ void topk_kernel() {
    __shared__ float key[NN];
    __shared__ int   val[NN];
    int b = blockIdx.x;
    for (int i = threadIdx.x; i < NN; i += blockDim.x) { key[i] = g_scores[b * NN + i]; val[i] = i; }
    __syncthreads();
    for (int k = 2; k <= NN; k <<= 1)
        for (int j = k >> 1; j > 0; j >>= 1) {
            for (int i = threadIdx.x; i < NN; i += blockDim.x) {
                int ixj = i ^ j;
                if (ixj > i) {
                    bool up = ((i & k) == 0);
                    float ki = key[i], kj = key[ixj];
                    if (up ? (ki > kj) : (ki < kj)) {
                        key[i] = kj; key[ixj] = ki;
                        int t = val[i]; val[i] = val[ixj]; val[ixj] = t;
                    }
                }
            }
            __syncthreads();
        }
    for (int i = threadIdx.x; i < KK; i += blockDim.x)
        g_sel[b * KK + i] = val[NN - 1 - i];
}

// ---------------------------------------------------------------------------
// 3) Gather selected rows + convert fp16 -> g_a
// ---------------------------------------------------------------------------
__global__ void gather_h_kernel(const float* __restrict__ x) {
    int m = blockIdx.x;
    int c = threadIdx.x;                 // 4 floats -> 4 halves each
    int tok = g_sel[m];
    size_t src = ((size_t)(m >> 11) * NN + tok) * DD + c * 4;
    float4 v = *reinterpret_cast<const float4*>(x + src);
    __half2 h0 = __floats2half2_rn(v.x, v.y);
    __half2 h1 = __floats2half2_rn(v.z, v.w);
    uint2 pk;
    pk.x = *reinterpret_cast<uint32_t*>(&h0);
    pk.y = *reinterpret_cast<uint32_t*>(&h1);
    *reinterpret_cast<uint2*>(g_a + (size_t)m * DD + c * 4) = pk;
}

// ---------------------------------------------------------------------------
// 4) Transpose + convert fp16: dst[c*R + r] = h(src[r*C + c])
// ---------------------------------------------------------------------------
template <int R, int C, int WHICH>
__global__ void transpose_h_kernel(const float* __restrict__ src) {
    __shared__ float t[32][33];
    __half* dst = WHICH == 0 ? g_w1t : g_w2t;
    int bx = blockIdx.x * 32, by = blockIdx.y * 32;
    int tx = threadIdx.x, ty = threadIdx.y;
#pragma unroll
    for (int i = 0; i < 32; i += 8)
        t[ty + i][tx] = src[(size_t)(by + ty + i) * C + bx + tx];
    __syncthreads();
#pragma unroll
    for (int i = 0; i < 32; i += 8)
        dst[(size_t)(bx + ty + i) * R + by + tx] = __float2half_rn(t[tx][ty + i]);
}

// ---------------------------------------------------------------------------
// fp16 mma.sync GEMM with ldmatrix fragments:
//   C[128x128 tile] = A[M,K] @ B[N,K]^T  (fp32 accumulate)
//   MODE 0: ffn1  A=g_a (K=1024), B=g_w1t  ->  g_h = h(gelu(C + b1))
//   MODE 1: ffn2  A=g_h (K=4096), B=g_w2t  ->  out[sel] = x[sel] + C + b2
// 256 threads, 8 warps 4(M) x 2(N), warp tile 32x64 = 2x8 m16n8k16 tiles.
// BK=64, 3-stage cp.async pipeline, ONE __syncthreads per K-iter.
// smem row pitch 72 halves (144 B): ldmatrix phases conflict-free
// (row i -> banks 4i..4i+3, exact 32-bank cover over 8 rows).
// ---------------------------------------------------------------------------
#define HPITCH_B 144                               // bytes per row (72 halves)
#define STG_BYTES (128 * HPITCH_B)                 // 18432 B per operand-stage
#define NSTG 3
#define GSMEM_SZ (2 * NSTG * STG_BYTES)            // 110592 B

__device__ __forceinline__ void ld_stage(uint32_t sb, int stage,
                                         const __half* __restrict__ A,
                                         const __half* __restrict__ Bw,
                                         int Kdim, int mt, int nt, int k0, int tid) {
    uint32_t abase = sb + stage * STG_BYTES;
    uint32_t bbase = sb + (NSTG + stage) * STG_BYTES;
    int row = tid >> 3, ch = tid & 7;              // 8 x 16B chunks cover 64 halves
    const __half* ag = A  + (size_t)(mt * 128 + row) * Kdim + k0 + ch * 8;
    const __half* bg = Bw + (size_t)(nt * 128 + row) * Kdim + k0 + ch * 8;
    uint32_t off = row * HPITCH_B + ch * 16;
#pragma unroll
    for (int i = 0; i < 4; ++i) {
        CP_ASYNC16(abase + off + i * 32 * HPITCH_B, ag + (size_t)(i * 32) * Kdim);
        CP_ASYNC16(bbase + off + i * 32 * HPITCH_B, bg + (size_t)(i * 32) * Kdim);
    }
}

template <int MODE>
__global__ __launch_bounds__(256, 2)
void mma_gemm(const float* __restrict__ bias,
              const float* __restrict__ xin,
              float* __restrict__ outp) {
    extern __shared__ uint32_t smw[];
    const __half* A    = (MODE == 0) ? g_a   : g_h;
    const __half* Bw   = (MODE == 0) ? g_w1t : g_w2t;
    const int     Kdim = (MODE == 0) ? DD : DFFN;
    const int     KT   = Kdim / 64;

    int tid = threadIdx.x, lane = tid & 31, wid = tid >> 5;
    int wm = wid >> 1, wn = wid & 1;               // warp tile: rows wm*32, cols wn*64
    int mt = blockIdx.y, nt = blockIdx.x;
    uint32_t sb = smem_u32(smw);

    // ldmatrix per-lane offsets: matrix order {r0-7,k0-7},{r8-15,k0-7},{r0-7,k8-15},{r8-15,k8-15}
    int lrow = ((lane >> 3) & 1) * 8 + (lane & 7);
    int koff = (lane >= 16) ? 16 : 0;              // bytes (8 halves)
    uint32_t a_off[2], b_off[4];
#pragma unroll
    for (int mi = 0; mi < 2; ++mi)
        a_off[mi] = (wm * 32 + mi * 16 + lrow) * HPITCH_B + koff;
#pragma unroll
    for (int p = 0; p < 4; ++p)
        b_off[p] = (wn * 64 + p * 16 + lrow) * HPITCH_B + koff;

    float acc[2][8][4];
#pragma unroll
    for (int mi = 0; mi < 2; ++mi)
#pragma unroll
        for (int ni = 0; ni < 8; ++ni)
#pragma unroll
            for (int q = 0; q < 4; ++q) acc[mi][ni][q] = 0.0f;

    // prologue: 2 stages in flight
    ld_stage(sb, 0, A, Bw, Kdim, mt, nt, 0, tid);
    CP_COMMIT();
    ld_stage(sb, 1, A, Bw, Kdim, mt, nt, 64, tid);
    CP_COMMIT();

    int stage = 0;
    for (int k = 0; k < KT; ++k) {
        CP_WAIT1();
        __syncthreads();

        int pstage = stage + 2 >= NSTG ? stage + 2 - NSTG : stage + 2;
        if (k + 2 < KT)
            ld_stage(sb, pstage, A, Bw, Kdim, mt, nt, (k + 2) * 64, tid);
        CP_COMMIT();

        uint32_t As_addr = sb + stage * STG_BYTES;
        uint32_t Bs_addr = sb + (NSTG + stage) * STG_BYTES;
#pragma unroll
        for (int ks = 0; ks < 4; ++ks) {           // 4 x K=16
            uint32_t a[2][4];
            LDSM_X4(a[0][0], a[0][1], a[0][2], a[0][3], As_addr + a_off[0] + ks * 32);
            LDSM_X4(a[1][0], a[1][1], a[1][2], a[1][3], As_addr + a_off[1] + ks * 32);
#pragma unroll
            for (int p = 0; p < 4; ++p) {
                uint32_t b0, b1, b2, b3;           // = (ni0.b0, ni1.b0, ni0.b1, ni1.b1)
                LDSM_X4(b0, b1, b2, b3, Bs_addr + b_off[p] + ks * 32);
                MMA_F16(acc[0][2 * p + 0], a[0], b0, b2);
                MMA_F16(acc[0][2 * p + 1], a[0], b1, b3);
                MMA_F16(acc[1][2 * p + 0], a[1], b0, b2);
                MMA_F16(acc[1][2 * p + 1], a[1], b1, b3);
            }
        }
        stage = stage + 1 == NSTG ? 0 : stage + 1;
    }

    // ---------------- Epilogue ----------------
    int r = lane >> 2, c = lane & 3;
    // c0/c1: row = r, cols 2c,2c+1 ; c2/c3: row = r+8
    if (MODE == 0) {
#pragma unroll
        for (int mi = 0; mi < 2; ++mi) {
#pragma unroll
            for (int half = 0; half < 2; ++half) {
                int m = mt * 128 + wm * 32 + mi * 16 + half * 8 + r;
                __half* hrow = g_h + (size_t)m * DFFN;
#pragma unroll
                for (int ni = 0; ni < 8; ++ni) {
                    int n = nt * 128 + wn * 64 + ni * 8 + c * 2;
                    float v0 = gelu_tanh(acc[mi][ni][half * 2 + 0] + bias[n]);
                    float v1 = gelu_tanh(acc[mi][ni][half * 2 + 1] + bias[n + 1]);
                    __half2 hv = __floats2half2_rn(v0, v1);
                    *reinterpret_cast<__half2*>(hrow + n) = hv;
                }
            }
        }
    } else {
#pragma unroll
        for (int mi = 0; mi < 2; ++mi) {
#pragma unroll
            for (int half = 0; half < 2; ++half) {
                int m = mt * 128 + wm * 32 + mi * 16 + half * 8 + r;
                int tok = g_sel[m];
                size_t base = ((size_t)(m >> 11) * NN + tok) * DD;
#pragma unroll
                for (int ni = 0; ni < 8; ++ni) {
                    int n = nt * 128 + wn * 64 + ni * 8 + c * 2;
                    float2 xv = *reinterpret_cast<const float2*>(xin + base + n);
                    float2 w;
                    w.x = xv.x + acc[mi][ni][half * 2 + 0] + bias[n];
                    w.y = xv.y + acc[mi][ni][half * 2 + 1] + bias[n + 1];
                    *reinterpret_cast<float2*>(outp + base + n) = w;
                }
            }
        }
    }
}

// ---------------------------------------------------------------------------
// Launch: x, gate_w, w1, b1, w2, b2, k
// ---------------------------------------------------------------------------
extern "C" void kernel_launch(void* const* d_in, const int* in_sizes, int n_in,
                              void* d_out, int out_size) {
    const float* x  = (const float*)d_in[0];
    const float* gw = (const float*)d_in[1];
    const float* w1 = (const float*)d_in[2];
    const float* b1 = (const float*)d_in[3];
    const float* w2 = (const float*)d_in[4];
    const float* b2 = (const float*)d_in[5];
    float* out = (float*)d_out;

    cudaFuncSetAttribute(mma_gemm<0>, cudaFuncAttributeMaxDynamicSharedMemorySize, GSMEM_SZ);
    cudaFuncSetAttribute(mma_gemm<1>, cudaFuncAttributeMaxDynamicSharedMemorySize, GSMEM_SZ);

    scores_copy_kernel<<<(BB * NN) / 8, 256>>>(x, gw, out);                            // 1
    topk_kernel<<<BB, 1024>>>();                                                       // 2
    gather_h_kernel<<<MM, 256>>>(x);                                                   // 3
    transpose_h_kernel<DD, DFFN, 0><<<dim3(DFFN / 32, DD / 32), dim3(32, 8)>>>(w1);    // 4
    transpose_h_kernel<DFFN, DD, 1><<<dim3(DD / 32, DFFN / 32), dim3(32, 8)>>>(w2);    // 5
    // GEMM1: g_a[8192,1024] @ w1 -> g_h[8192,4096]  (gelu fused, fp16 out)
    mma_gemm<0><<<dim3(DFFN / 128, MM / 128), 256, GSMEM_SZ>>>(b1, nullptr, nullptr);  // 6
    // GEMM2: g_h @ w2 + residual -> scattered into out
    mma_gemm<1><<<dim3(DD / 128, MM / 128), 256, GSMEM_SZ>>>(b2, x, out);              // 7
}

// round 9
// speedup vs baseline: 1.0082x; 1.0082x over previous
#include <cuda_runtime.h>
#include <cuda_fp16.h>
#include <cstdint>
#include <math.h>

// Problem constants (MoDRouter_48387101556956: fixed shapes)
#define BB   4
#define NN   4096
#define DD   1024
#define DFFN 4096
#define KK   2048
#define MM   (BB * KK)   // 8192 selected tokens total

// ---------------------------------------------------------------------------
// Device scratch
// ---------------------------------------------------------------------------
__device__ float  g_scores[BB * NN];
__device__ int    g_sel[MM];                       // selected token idx per (b,j)
__device__ __half g_a[(size_t)MM * DD];            // gathered fp16 A (16 MB)
__device__ __half g_w1t[(size_t)DFFN * DD];        // w1^T (n-major, K contig), fp16
__device__ __half g_w2t[(size_t)DD * DFFN];        // w2^T (n-major, K contig), fp16
__device__ __half g_h[(size_t)MM * DFFN];          // gelu(x@w1+b1), fp16 (64 MB)

// ---------------------------------------------------------------------------
// Helpers
// ---------------------------------------------------------------------------
__device__ __forceinline__ uint32_t smem_u32(const void* p) {
    uint32_t a;
    asm("{ .reg .u64 t; cvta.to.shared.u64 t, %1; cvt.u32.u64 %0, t; }" : "=r"(a) : "l"(p));
    return a;
}
__device__ __forceinline__ float gelu_tanh(float u) {
    float t = tanhf(0.7978845608028654f * (u + 0.044715f * u * u * u));
    return 0.5f * u * (1.0f + t);
}

#define CP_ASYNC16(dst, src) \
    asm volatile("cp.async.cg.shared.global [%0], [%1], 16;" :: "r"(dst), "l"(src) : "memory")
#define CP_COMMIT() asm volatile("cp.async.commit_group;" ::: "memory")
#define CP_WAIT1()  asm volatile("cp.async.wait_group 1;" ::: "memory")

// m16n8k16 row.col fp16 MMA, fp32 accumulate (base-ISA, legal on sm_103)
#define MMA_F16(c, a, b0, b1)                                                         \
    asm volatile("mma.sync.aligned.m16n8k16.row.col.f32.f16.f16.f32 "                 \
                 "{%0,%1,%2,%3}, {%4,%5,%6,%7}, {%8,%9}, {%0,%1,%2,%3};"              \
                 : "+f"((c)[0]), "+f"((c)[1]), "+f"((c)[2]), "+f"((c)[3])             \
                 : "r"((a)[0]), "r"((a)[1]), "r"((a)[2]), "r"((a)[3]), "r"(b0), "r"(b1))

// ldmatrix 4x m8n8 b16 (non-transposed)
#define LDSM_X4(r0, r1, r2, r3, addr)                                                 \
    asm volatile("ldmatrix.sync.aligned.m8n8.x4.shared.b16 {%0,%1,%2,%3}, [%4];"      \
                 : "=r"(r0), "=r"(r1), "=r"(r2), "=r"(r3) : "r"(addr))

// ---------------------------------------------------------------------------
// 1) Gate scores + out=x copy fused — one warp per row (reads the row anyway)
// ---------------------------------------------------------------------------
__global__ void scores_copy_kernel(const float* __restrict__ x,
                                   const float* __restrict__ gw,
                                   float* __restrict__ out) {
    int gwarp = (blockIdx.x * blockDim.x + threadIdx.x) >> 5;
    int lane  = threadIdx.x & 31;
    if (gwarp >= BB * NN) return;
    const float4* xr = reinterpret_cast<const float4*>(x + (size_t)gwarp * DD);
    float4*       orow = reinterpret_cast<float4*>(out + (size_t)gwarp * DD);
    const float4* g4 = reinterpret_cast<const float4*>(gw);
    float s = 0.0f;
#pragma unroll
    for (int i = 0; i < DD / 4 / 32; ++i) {
        float4 a = xr[lane + i * 32];
        float4 b = g4[lane + i * 32];
        orow[lane + i * 32] = a;                      // fused copy
        s += a.x * b.x + a.y * b.y + a.z * b.z + a.w * b.w;
    }
#pragma unroll
    for (int o = 16; o; o >>= 1) s += __shfl_xor_sync(0xFFFFFFFFu, s, o);
    if (lane == 0) g_scores[gwarp] = s;
}

// ---------------------------------------------------------------------------
// 2) Per-batch exact top-K via byte-wise radix select (1 CTA per batch).
//    Selection set = top-K by (score desc, index asc) — matches jax top_k.
//    g_sel order within a batch is arbitrary (rows are independent downstream).
// ---------------------------------------------------------------------------
__global__ void topk_select_kernel() {
    __shared__ uint32_t keys[NN];                  // 16 KB
    __shared__ int      eqidx[NN];                 // 16 KB (worst case)
    __shared__ int      hist[256];
    __shared__ int      sh_boundary, sh_remaining, sh_outcnt, sh_eqn;
    __shared__ uint32_t sh_prefix;
    int b = blockIdx.x, tid = threadIdx.x, nthr = blockDim.x;

    for (int i = tid; i < NN; i += nthr) {
        uint32_t u = __float_as_uint(g_scores[b * NN + i]);
        u = (u & 0x80000000u) ? ~u : (u | 0x80000000u);   // monotone map
        keys[i] = u;
    }
    if (tid == 0) { sh_remaining = KK; sh_prefix = 0u; sh_outcnt = 0; }
    __syncthreads();

    for (int byte = 3; byte >= 0; --byte) {
        if (tid < 256) hist[tid] = 0;
        __syncthreads();
        int shift = byte * 8;
        uint32_t pfx = sh_prefix;
        for (int i = tid; i < NN; i += nthr) {
            uint32_t u = keys[i];
            bool active = (byte == 3) || ((u >> (shift + 8)) == pfx);
            if (active) atomicAdd(&hist[(u >> shift) & 0xFF], 1);
        }
        __syncthreads();
        if (tid == 0) {
            int R = sh_remaining, cum = 0, v = 255;
            for (; v > 0; --v) {
                if (cum + hist[v] >= R) break;
                cum += hist[v];
            }
            sh_boundary  = v;
            sh_remaining = R - cum;                // to take from bucket v
            sh_prefix    = (pfx << 8) | (uint32_t)v;
        }
        __syncthreads();
        int bnd = sh_boundary;
        for (int i = tid; i < NN; i += nthr) {
            uint32_t u = keys[i];
            bool active = (byte == 3) || ((u >> (shift + 8)) == pfx);
            if (active && (int)((u >> shift) & 0xFF) > bnd) {
                int slot = atomicAdd(&sh_outcnt, 1);
                g_sel[b * KK + slot] = i;
            }
        }
        __syncthreads();
    }

    // Exact handling of keys == threshold: smallest indices win (jax tie rule).
    if (tid == 0) sh_eqn = 0;
    __syncthreads();
    uint32_t T = sh_prefix;
    for (int i = tid; i < NN; i += nthr)
        if (keys[i] == T) eqidx[atomicAdd(&sh_eqn, 1)] = i;
    __syncthreads();
    int R = sh_remaining, en = sh_eqn;
    for (int j = tid; j < en; j += nthr) {
        int idx = eqidx[j], rank = 0;
        for (int t = 0; t < en; ++t) rank += (eqidx[t] < idx);
        if (rank < R) {
            int slot = atomicAdd(&sh_outcnt, 1);
            g_sel[b * KK + slot] = idx;
        }
    }
}

// ---------------------------------------------------------------------------
// 3) Gather selected rows + convert fp16 -> g_a
// ---------------------------------------------------------------------------
__global__ void gather_h_kernel(const float* __restrict__ x) {
    int m = blockIdx.x;
    int c = threadIdx.x;                 // 4 floats -> 4 halves each
    int tok = g_sel[m];
    size_t src = ((size_t)(m >> 11) * NN + tok) * DD + c * 4;
    float4 v = *reinterpret_cast<const float4*>(x + src);
    __half2 h0 = __floats2half2_rn(v.x, v.y);
    __half2 h1 = __floats2half2_rn(v.z, v.w);
    uint2 pk;
    pk.x = *reinterpret_cast<uint32_t*>(&h0);
    pk.y = *reinterpret_cast<uint32_t*>(&h1);
    *reinterpret_cast<uint2*>(g_a + (size_t)m * DD + c * 4) = pk;
}

// ---------------------------------------------------------------------------
// 4) Transpose + convert fp16: dst[c*R + r] = h(src[r*C + c])
// ---------------------------------------------------------------------------
template <int R, int C, int WHICH>
__global__ void transpose_h_kernel(const float* __restrict__ src) {
    __shared__ float t[32][33];
    __half* dst = WHICH == 0 ? g_w1t : g_w2t;
    int bx = blockIdx.x * 32, by = blockIdx.y * 32;
    int tx = threadIdx.x, ty = threadIdx.y;
#pragma unroll
    for (int i = 0; i < 32; i += 8)
        t[ty + i][tx] = src[(size_t)(by + ty + i) * C + bx + tx];
    __syncthreads();
#pragma unroll
    for (int i = 0; i < 32; i += 8)
        dst[(size_t)(bx + ty + i) * R + by + tx] = __float2half_rn(t[tx][ty + i]);
}

// ---------------------------------------------------------------------------
// fp16 mma.sync GEMM, CTA tile 256x128, warp tile 64x64 (8 warps = 4M x 2N):
//   C = A[M,K] @ B[N,K]^T  (fp32 accumulate)
//   MODE 0: ffn1  A=g_a (K=1024), B=g_w1t  ->  g_h = h(gelu(C + b1))
//   MODE 1: ffn2  A=g_h (K=4096), B=g_w2t  ->  out[sel] = x[sel] + C + b2
// BK=64, 3-stage cp.async pipeline, ONE __syncthreads per K-iter.
// Fragment reads/K-iter: 8 x (64+64) x 128B = 128KB for 2M MACs -> 88 B/cyc,
// below the 128 B/cyc smem port: tensor pipe becomes the binder.
// Row pitch 144B keeps every ldmatrix phase conflict-free (banks 4*row mod 32).
// ---------------------------------------------------------------------------
#define HPITCH_B 144                               // bytes per row (72 halves)
#define A_STG (256 * HPITCH_B)                     // 36864 B
#define B_STG (128 * HPITCH_B)                     // 18432 B
#define NSTG 3
#define GSMEM_SZ (NSTG * (A_STG + B_STG))          // 165888 B

__device__ __forceinline__ void ld_stage(uint32_t sb, int stage,
                                         const __half* __restrict__ A,
                                         const __half* __restrict__ Bw,
                                         int Kdim, int mt, int nt, int k0, int tid) {
    uint32_t abase = sb + stage * A_STG;
    uint32_t bbase = sb + NSTG * A_STG + stage * B_STG;
    // A: 256 rows x 8 chunks = 2048 -> 8 per thread
#pragma unroll
    for (int i = 0; i < 8; ++i) {
        int lin = i * 256 + tid;
        int row = lin >> 3, ch = lin & 7;
        CP_ASYNC16(abase + row * HPITCH_B + ch * 16,
                   A + (size_t)(mt * 256 + row) * Kdim + k0 + ch * 8);
    }
    // B: 128 rows x 8 chunks = 1024 -> 4 per thread
#pragma unroll
    for (int i = 0; i < 4; ++i) {
        int lin = i * 256 + tid;
        int row = lin >> 3, ch = lin & 7;
        CP_ASYNC16(bbase + row * HPITCH_B + ch * 16,
                   Bw + (size_t)(nt * 128 + row) * Kdim + k0 + ch * 8);
    }
}

template <int MODE>
__global__ __launch_bounds__(256, 1)
void mma_gemm(const float* __restrict__ bias,
              const float* __restrict__ xin,
              float* __restrict__ outp) {
    extern __shared__ uint32_t smw[];
    const __half* A    = (MODE == 0) ? g_a   : g_h;
    const __half* Bw   = (MODE == 0) ? g_w1t : g_w2t;
    const int     Kdim = (MODE == 0) ? DD : DFFN;
    const int     KT   = Kdim / 64;

    int tid = threadIdx.x, lane = tid & 31, wid = tid >> 5;
    int wm = wid >> 1, wn = wid & 1;               // warp tile: rows wm*64, cols wn*64
    int mt = blockIdx.y, nt = blockIdx.x;
    uint32_t sb = smem_u32(smw);

    // ldmatrix lane offsets: matrices {r0-7,k0-7},{r8-15,k0-7},{r0-7,k8-15},{r8-15,k8-15}
    int lrow = ((lane >> 3) & 1) * 8 + (lane & 7);
    int koff = (lane >= 16) ? 16 : 0;
    uint32_t a_off[4], b_off[4];
#pragma unroll
    for (int mi = 0; mi < 4; ++mi)
        a_off[mi] = (wm * 64 + mi * 16 + lrow) * HPITCH_B + koff;
#pragma unroll
    for (int p = 0; p < 4; ++p)
        b_off[p] = (wn * 64 + p * 16 + lrow) * HPITCH_B + koff;

    float acc[4][8][4];
#pragma unroll
    for (int mi = 0; mi < 4; ++mi)
#pragma unroll
        for (int ni = 0; ni < 8; ++ni)
#pragma unroll
            for (int q = 0; q < 4; ++q) acc[mi][ni][q] = 0.0f;

    // prologue: 2 stages in flight
    ld_stage(sb, 0, A, Bw, Kdim, mt, nt, 0, tid);
    CP_COMMIT();
    ld_stage(sb, 1, A, Bw, Kdim, mt, nt, 64, tid);
    CP_COMMIT();

    int stage = 0;
    for (int k = 0; k < KT; ++k) {
        CP_WAIT1();
        __syncthreads();

        int pstage = stage + 2 >= NSTG ? stage + 2 - NSTG : stage + 2;
        if (k + 2 < KT)
            ld_stage(sb, pstage, A, Bw, Kdim, mt, nt, (k + 2) * 64, tid);
        CP_COMMIT();

        uint32_t As_addr = sb + stage * A_STG;
        uint32_t Bs_addr = sb + NSTG * A_STG + stage * B_STG;
#pragma unroll
        for (int ks = 0; ks < 4; ++ks) {           // 4 x K=16
            uint32_t a[4][4];
#pragma unroll
            for (int mi = 0; mi < 4; ++mi)
                LDSM_X4(a[mi][0], a[mi][1], a[mi][2], a[mi][3],
                        As_addr + a_off[mi] + ks * 32);
#pragma unroll
            for (int p = 0; p < 4; ++p) {
                uint32_t b0, b1, b2, b3;           // (ni0.k0, ni1.k0, ni0.k8, ni1.k8)
                LDSM_X4(b0, b1, b2, b3, Bs_addr + b_off[p] + ks * 32);
#pragma unroll
                for (int mi = 0; mi < 4; ++mi) {
                    MMA_F16(acc[mi][2 * p + 0], a[mi], b0, b2);
                    MMA_F16(acc[mi][2 * p + 1], a[mi], b1, b3);
                }
            }
        }
        stage = stage + 1 == NSTG ? 0 : stage + 1;
    }

    // ---------------- Epilogue ----------------
    int r = lane >> 2, c = lane & 3;
    // c0/c1: row = r, cols 2c,2c+1 ; c2/c3: row = r+8
    if (MODE == 0) {
#pragma unroll
        for (int mi = 0; mi < 4; ++mi) {
#pragma unroll
            for (int half = 0; half < 2; ++half) {
                int m = mt * 256 + wm * 64 + mi * 16 + half * 8 + r;
                __half* hrow = g_h + (size_t)m * DFFN;
#pragma unroll
                for (int ni = 0; ni < 8; ++ni) {
                    int n = nt * 128 + wn * 64 + ni * 8 + c * 2;
                    float v0 = gelu_tanh(acc[mi][ni][half * 2 + 0] + bias[n]);
                    float v1 = gelu_tanh(acc[mi][ni][half * 2 + 1] + bias[n + 1]);
                    __half2 hv = __floats2half2_rn(v0, v1);
                    *reinterpret_cast<__half2*>(hrow + n) = hv;
                }
            }
        }
    } else {
#pragma unroll
        for (int mi = 0; mi < 4; ++mi) {
#pragma unroll
            for (int half = 0; half < 2; ++half) {
                int m = mt * 256 + wm * 64 + mi * 16 + half * 8 + r;
                int tok = g_sel[m];
                size_t base = ((size_t)(m >> 11) * NN + tok) * DD;
#pragma unroll
                for (int ni = 0; ni < 8; ++ni) {
                    int n = nt * 128 + wn * 64 + ni * 8 + c * 2;
                    float2 xv = *reinterpret_cast<const float2*>(xin + base + n);
                    float2 w;
                    w.x = xv.x + acc[mi][ni][half * 2 + 0] + bias[n];
                    w.y = xv.y + acc[mi][ni][half * 2 + 1] + bias[n + 1];
                    *reinterpret_cast<float2*>(outp + base + n) = w;
                }
            }
        }
    }
}

// ---------------------------------------------------------------------------
// Launch: x, gate_w, w1, b1, w2, b2, k
// ---------------------------------------------------------------------------
extern "C" void kernel_launch(void* const* d_in, const int* in_sizes, int n_in,
                              void* d_out, int out_size) {
    const float* x  = (const float*)d_in[0];
    const float* gw = (const float*)d_in[1];
    const float* w1 = (const float*)d_in[2];
    const float* b1 = (const float*)d_in[3];
    const float* w2 = (const float*)d_in[4];
    const float* b2 = (const float*)d_in[5];
    float* out = (float*)d_out;

    cudaFuncSetAttribute(mma_gemm<0>, cudaFuncAttributeMaxDynamicSharedMemorySize, GSMEM_SZ);
    cudaFuncSetAttribute(mma_gemm<1>, cudaFuncAttributeMaxDynamicSharedMemorySize, GSMEM_SZ);

    scores_copy_kernel<<<(BB * NN) / 8, 256>>>(x, gw, out);                            // 1
    topk_select_kernel<<<BB, 1024>>>();                                                // 2
    gather_h_kernel<<<MM, 256>>>(x);                                                   // 3
    transpose_h_kernel<DD, DFFN, 0><<<dim3(DFFN / 32, DD / 32), dim3(32, 8)>>>(w1);    // 4
    transpose_h_kernel<DFFN, DD, 1><<<dim3(DD / 32, DFFN / 32), dim3(32, 8)>>>(w2);    // 5
    // GEMM1: g_a[8192,1024] @ w1 -> g_h[8192,4096]  (gelu fused, fp16 out)
    mma_gemm<0><<<dim3(DFFN / 128, MM / 256), 256, GSMEM_SZ>>>(b1, nullptr, nullptr);  // 6
    // GEMM2: g_h @ w2 + residual -> scattered into out
    mma_gemm<1><<<dim3(DD / 128, MM / 256), 256, GSMEM_SZ>>>(b2, x, out);              // 7
}

// round 10
// speedup vs baseline: 1.0401x; 1.0317x over previous
#include <cuda_runtime.h>
#include <cuda_fp16.h>
#include <cstdint>
#include <math.h>

// Problem constants (MoDRouter_48387101556956: fixed shapes)
#define BB   4
#define NN   4096
#define DD   1024
#define DFFN 4096
#define KK   2048
#define MM   (BB * KK)   // 8192 selected tokens total

// ---------------------------------------------------------------------------
// Device scratch
// ---------------------------------------------------------------------------
__device__ float  g_scores[BB * NN];
__device__ int    g_sel[MM];                       // selected token idx per (b,j)
__device__ __half g_a[(size_t)MM * DD];            // gathered fp16 A (16 MB)
__device__ __half g_w1t[(size_t)DFFN * DD];        // w1^T (n-major, K contig), fp16
__device__ __half g_w2t[(size_t)DD * DFFN];        // w2^T (n-major, K contig), fp16
__device__ __half g_h[(size_t)MM * DFFN];          // gelu(x@w1+b1), fp16 (64 MB)

// ---------------------------------------------------------------------------
// Helpers
// ---------------------------------------------------------------------------
__device__ __forceinline__ uint32_t smem_u32(const void* p) {
    uint32_t a;
    asm("{ .reg .u64 t; cvta.to.shared.u64 t, %1; cvt.u32.u64 %0, t; }" : "=r"(a) : "l"(p));
    return a;
}
// gelu-tanh with HW MUFU tanh (sm_75+): |err| <= ~2^-11, inside error budget
__device__ __forceinline__ float gelu_fast(float u) {
    float arg = 0.7978845608028654f * (u + 0.044715f * u * u * u);
    float t;
    asm("tanh.approx.f32 %0, %1;" : "=f"(t) : "f"(arg));
    return 0.5f * u * (1.0f + t);
}

#define CP_ASYNC16(dst, src) \
    asm volatile("cp.async.cg.shared.global [%0], [%1], 16;" :: "r"(dst), "l"(src) : "memory")
#define CP_COMMIT() asm volatile("cp.async.commit_group;" ::: "memory")
#define CP_WAIT1()  asm volatile("cp.async.wait_group 1;" ::: "memory")

// m16n8k16 row.col fp16 MMA, fp32 accumulate (base-ISA, legal on sm_103)
#define MMA_F16(c, a, b0, b1)                                                         \
    asm volatile("mma.sync.aligned.m16n8k16.row.col.f32.f16.f16.f32 "                 \
                 "{%0,%1,%2,%3}, {%4,%5,%6,%7}, {%8,%9}, {%0,%1,%2,%3};"              \
                 : "+f"((c)[0]), "+f"((c)[1]), "+f"((c)[2]), "+f"((c)[3])             \
                 : "r"((a)[0]), "r"((a)[1]), "r"((a)[2]), "r"((a)[3]), "r"(b0), "r"(b1))

// ldmatrix 4x m8n8 b16 (non-transposed)
#define LDSM_X4(r0, r1, r2, r3, addr)                                                 \
    asm volatile("ldmatrix.sync.aligned.m8n8.x4.shared.b16 {%0,%1,%2,%3}, [%4];"      \
                 : "=r"(r0), "=r"(r1), "=r"(r2), "=r"(r3) : "r"(addr))

// ---------------------------------------------------------------------------
// 1) FUSED prepass: scores+copy (CTAs [0,2048)), w1^T (CTAs [2048,6144)),
//    w2^T (CTAs [6144,10240)) — all independent, one wave-parallel launch.
// ---------------------------------------------------------------------------
__device__ __forceinline__ void transpose_body(const float* __restrict__ src,
                                               __half* __restrict__ dst,
                                               int R, int C, int bx, int by,
                                               int tx, int ty, float (*t)[33]) {
#pragma unroll
    for (int i = 0; i < 32; i += 8)
        t[ty + i][tx] = src[(size_t)(by + ty + i) * C + bx + tx];
    __syncthreads();
#pragma unroll
    for (int i = 0; i < 32; i += 8)
        dst[(size_t)(bx + ty + i) * R + by + tx] = __float2half_rn(t[tx][ty + i]);
}

__global__ void prepass_kernel(const float* __restrict__ x,
                               const float* __restrict__ gw,
                               const float* __restrict__ w1,
                               const float* __restrict__ w2,
                               float* __restrict__ out) {
    __shared__ float t[32][33];
    int bid = blockIdx.x, tid = threadIdx.x;
    if (bid < 2048) {
        // scores + copy: one warp per row, 8 rows per CTA
        int gwarp = bid * 8 + (tid >> 5);
        int lane  = tid & 31;
        const float4* xr = reinterpret_cast<const float4*>(x + (size_t)gwarp * DD);
        float4*       orow = reinterpret_cast<float4*>(out + (size_t)gwarp * DD);
        const float4* g4 = reinterpret_cast<const float4*>(gw);
        float s = 0.0f;
#pragma unroll
        for (int i = 0; i < DD / 4 / 32; ++i) {
            float4 a = xr[lane + i * 32];
            float4 b = g4[lane + i * 32];
            orow[lane + i * 32] = a;
            s += a.x * b.x + a.y * b.y + a.z * b.z + a.w * b.w;
        }
#pragma unroll
        for (int o = 16; o; o >>= 1) s += __shfl_xor_sync(0xFFFFFFFFu, s, o);
        if (lane == 0) g_scores[gwarp] = s;
    } else if (bid < 2048 + 4096) {
        // w1 [DD, DFFN] -> g_w1t [DFFN, DD]
        int r = bid - 2048;
        int bx = (r & 127) * 32, by = (r >> 7) * 32;     // C/32=128 x-blocks
        transpose_body(w1, g_w1t, DD, DFFN, bx, by, tid & 31, tid >> 5, t);
    } else {
        // w2 [DFFN, DD] -> g_w2t [DD, DFFN]
        int r = bid - 6144;
        int bx = (r & 31) * 32, by = (r >> 5) * 32;      // C/32=32 x-blocks
        transpose_body(w2, g_w2t, DFFN, DD, bx, by, tid & 31, tid >> 5, t);
    }
}

// ---------------------------------------------------------------------------
// 2) Per-batch exact top-K via byte-wise radix select (1 CTA per batch).
// ---------------------------------------------------------------------------
__global__ void topk_select_kernel() {
    __shared__ uint32_t keys[NN];
    __shared__ int      eqidx[NN];
    __shared__ int      hist[256];
    __shared__ int      sh_boundary, sh_remaining, sh_outcnt, sh_eqn;
    __shared__ uint32_t sh_prefix;
    int b = blockIdx.x, tid = threadIdx.x, nthr = blockDim.x;

    for (int i = tid; i < NN; i += nthr) {
        uint32_t u = __float_as_uint(g_scores[b * NN + i]);
        u = (u & 0x80000000u) ? ~u : (u | 0x80000000u);   // monotone map
        keys[i] = u;
    }
    if (tid == 0) { sh_remaining = KK; sh_prefix = 0u; sh_outcnt = 0; }
    __syncthreads();

    for (int byte = 3; byte >= 0; --byte) {
        if (tid < 256) hist[tid] = 0;
        __syncthreads();
        int shift = byte * 8;
        uint32_t pfx = sh_prefix;
        for (int i = tid; i < NN; i += nthr) {
            uint32_t u = keys[i];
            bool active = (byte == 3) || ((u >> (shift + 8)) == pfx);
            if (active) atomicAdd(&hist[(u >> shift) & 0xFF], 1);
        }
        __syncthreads();
        if (tid == 0) {
            int R = sh_remaining, cum = 0, v = 255;
            for (; v > 0; --v) {
                if (cum + hist[v] >= R) break;
                cum += hist[v];
            }
            sh_boundary  = v;
            sh_remaining = R - cum;
            sh_prefix    = (pfx << 8) | (uint32_t)v;
        }
        __syncthreads();
        int bnd = sh_boundary;
        for (int i = tid; i < NN; i += nthr) {
            uint32_t u = keys[i];
            bool active = (byte == 3) || ((u >> (shift + 8)) == pfx);
            if (active && (int)((u >> shift) & 0xFF) > bnd) {
                int slot = atomicAdd(&sh_outcnt, 1);
                g_sel[b * KK + slot] = i;
            }
        }
        __syncthreads();
    }

    if (tid == 0) sh_eqn = 0;
    __syncthreads();
    uint32_t T = sh_prefix;
    for (int i = tid; i < NN; i += nthr)
        if (keys[i] == T) eqidx[atomicAdd(&sh_eqn, 1)] = i;
    __syncthreads();
    int R = sh_remaining, en = sh_eqn;
    for (int j = tid; j < en; j += nthr) {
        int idx = eqidx[j], rank = 0;
        for (int t = 0; t < en; ++t) rank += (eqidx[t] < idx);
        if (rank < R) {
            int slot = atomicAdd(&sh_outcnt, 1);
            g_sel[b * KK + slot] = idx;
        }
    }
}

// ---------------------------------------------------------------------------
// 3) Gather selected rows + convert fp16 -> g_a
// ---------------------------------------------------------------------------
__global__ void gather_h_kernel(const float* __restrict__ x) {
    int m = blockIdx.x;
    int c = threadIdx.x;
    int tok = g_sel[m];
    size_t src = ((size_t)(m >> 11) * NN + tok) * DD + c * 4;
    float4 v = *reinterpret_cast<const float4*>(x + src);
    __half2 h0 = __floats2half2_rn(v.x, v.y);
    __half2 h1 = __floats2half2_rn(v.z, v.w);
    uint2 pk;
    pk.x = *reinterpret_cast<uint32_t*>(&h0);
    pk.y = *reinterpret_cast<uint32_t*>(&h1);
    *reinterpret_cast<uint2*>(g_a + (size_t)m * DD + c * 4) = pk;
}

// ---------------------------------------------------------------------------
// fp16 mma.sync GEMM, CTA tile 256x128, warp tile 64x64 (8 warps = 4M x 2N):
//   C = A[M,K] @ B[N,K]^T  (fp32 accumulate)
//   MODE 0: ffn1  A=g_a (K=1024), B=g_w1t  ->  g_h = h(gelu(C + b1))
//   MODE 1: ffn2  A=g_h (K=4096), B=g_w2t  ->  out[sel] = x[sel] + C + b2
// BK=64, 3-stage cp.async pipeline, ONE __syncthreads per K-iter.
// Mainloop is at the legacy-HMMA issue ceiling (rt~16): keep unchanged.
// ---------------------------------------------------------------------------
#define HPITCH_B 144                               // bytes per row (72 halves)
#define A_STG (256 * HPITCH_B)                     // 36864 B
#define B_STG (128 * HPITCH_B)                     // 18432 B
#define NSTG 3
#define GSMEM_SZ (NSTG * (A_STG + B_STG))          // 165888 B

__device__ __forceinline__ void ld_stage(uint32_t sb, int stage,
                                         const __half* __restrict__ A,
                                         const __half* __restrict__ Bw,
                                         int Kdim, int mt, int nt, int k0, int tid) {
    uint32_t abase = sb + stage * A_STG;
    uint32_t bbase = sb + NSTG * A_STG + stage * B_STG;
#pragma unroll
    for (int i = 0; i < 8; ++i) {
        int lin = i * 256 + tid;
        int row = lin >> 3, ch = lin & 7;
        CP_ASYNC16(abase + row * HPITCH_B + ch * 16,
                   A + (size_t)(mt * 256 + row) * Kdim + k0 + ch * 8);
    }
#pragma unroll
    for (int i = 0; i < 4; ++i) {
        int lin = i * 256 + tid;
        int row = lin >> 3, ch = lin & 7;
        CP_ASYNC16(bbase + row * HPITCH_B + ch * 16,
                   Bw + (size_t)(nt * 128 + row) * Kdim + k0 + ch * 8);
    }
}

template <int MODE>
__global__ __launch_bounds__(256, 1)
void mma_gemm(const float* __restrict__ bias,
              const float* __restrict__ xin,
              float* __restrict__ outp) {
    extern __shared__ uint32_t smw[];
    const __half* A    = (MODE == 0) ? g_a   : g_h;
    const __half* Bw   = (MODE == 0) ? g_w1t : g_w2t;
    const int     Kdim = (MODE == 0) ? DD : DFFN;
    const int     KT   = Kdim / 64;

    int tid = threadIdx.x, lane = tid & 31, wid = tid >> 5;
    int wm = wid >> 1, wn = wid & 1;
    int mt = blockIdx.y, nt = blockIdx.x;
    uint32_t sb = smem_u32(smw);

    int lrow = ((lane >> 3) & 1) * 8 + (lane & 7);
    int koff = (lane >= 16) ? 16 : 0;
    uint32_t a_off[4], b_off[4];
#pragma unroll
    for (int mi = 0; mi < 4; ++mi)
        a_off[mi] = (wm * 64 + mi * 16 + lrow) * HPITCH_B + koff;
#pragma unroll
    for (int p = 0; p < 4; ++p)
        b_off[p] = (wn * 64 + p * 16 + lrow) * HPITCH_B + koff;

    float acc[4][8][4];
#pragma unroll
    for (int mi = 0; mi < 4; ++mi)
#pragma unroll
        for (int ni = 0; ni < 8; ++ni)
#pragma unroll
            for (int q = 0; q < 4; ++q) acc[mi][ni][q] = 0.0f;

    ld_stage(sb, 0, A, Bw, Kdim, mt, nt, 0, tid);
    CP_COMMIT();
    ld_stage(sb, 1, A, Bw, Kdim, mt, nt, 64, tid);
    CP_COMMIT();

    int stage = 0;
    for (int k = 0; k < KT; ++k) {
        CP_WAIT1();
        __syncthreads();

        int pstage = stage + 2 >= NSTG ? stage + 2 - NSTG : stage + 2;
        if (k + 2 < KT)
            ld_stage(sb, pstage, A, Bw, Kdim, mt, nt, (k + 2) * 64, tid);
        CP_COMMIT();

        uint32_t As_addr = sb + stage * A_STG;
        uint32_t Bs_addr = sb + NSTG * A_STG + stage * B_STG;
#pragma unroll
        for (int ks = 0; ks < 4; ++ks) {
            uint32_t a[4][4];
#pragma unroll
            for (int mi = 0; mi < 4; ++mi)
                LDSM_X4(a[mi][0], a[mi][1], a[mi][2], a[mi][3],
                        As_addr + a_off[mi] + ks * 32);
#pragma unroll
            for (int p = 0; p < 4; ++p) {
                uint32_t b0, b1, b2, b3;
                LDSM_X4(b0, b1, b2, b3, Bs_addr + b_off[p] + ks * 32);
#pragma unroll
                for (int mi = 0; mi < 4; ++mi) {
                    MMA_F16(acc[mi][2 * p + 0], a[mi], b0, b2);
                    MMA_F16(acc[mi][2 * p + 1], a[mi], b1, b3);
                }
            }
        }
        stage = stage + 1 == NSTG ? 0 : stage + 1;
    }

    // ---------------- Epilogue ----------------
    int r = lane >> 2, c = lane & 3;
    if (MODE == 0) {
#pragma unroll
        for (int mi = 0; mi < 4; ++mi) {
#pragma unroll
            for (int half = 0; half < 2; ++half) {
                int m = mt * 256 + wm * 64 + mi * 16 + half * 8 + r;
                __half* hrow = g_h + (size_t)m * DFFN;
#pragma unroll
                for (int ni = 0; ni < 8; ++ni) {
                    int n = nt * 128 + wn * 64 + ni * 8 + c * 2;
                    float v0 = gelu_fast(acc[mi][ni][half * 2 + 0] + bias[n]);
                    float v1 = gelu_fast(acc[mi][ni][half * 2 + 1] + bias[n + 1]);
                    __half2 hv = __floats2half2_rn(v0, v1);
                    *reinterpret_cast<__half2*>(hrow + n) = hv;
                }
            }
        }
    } else {
#pragma unroll
        for (int mi = 0; mi < 4; ++mi) {
#pragma unroll
            for (int half = 0; half < 2; ++half) {
                int m = mt * 256 + wm * 64 + mi * 16 + half * 8 + r;
                int tok = g_sel[m];
                size_t base = ((size_t)(m >> 11) * NN + tok) * DD;
#pragma unroll
                for (int ni = 0; ni < 8; ++ni) {
                    int n = nt * 128 + wn * 64 + ni * 8 + c * 2;
                    float2 xv = *reinterpret_cast<const float2*>(xin + base + n);
                    float2 w;
                    w.x = xv.x + acc[mi][ni][half * 2 + 0] + bias[n];
                    w.y = xv.y + acc[mi][ni][half * 2 + 1] + bias[n + 1];
                    *reinterpret_cast<float2*>(outp + base + n) = w;
                }
            }
        }
    }
}

// ---------------------------------------------------------------------------
// Launch: x, gate_w, w1, b1, w2, b2, k
// ---------------------------------------------------------------------------
extern "C" void kernel_launch(void* const* d_in, const int* in_sizes, int n_in,
                              void* d_out, int out_size) {
    const float* x  = (const float*)d_in[0];
    const float* gw = (const float*)d_in[1];
    const float* w1 = (const float*)d_in[2];
    const float* b1 = (const float*)d_in[3];
    const float* w2 = (const float*)d_in[4];
    const float* b2 = (const float*)d_in[5];
    float* out = (float*)d_out;

    cudaFuncSetAttribute(mma_gemm<0>, cudaFuncAttributeMaxDynamicSharedMemorySize, GSMEM_SZ);
    cudaFuncSetAttribute(mma_gemm<1>, cudaFuncAttributeMaxDynamicSharedMemorySize, GSMEM_SZ);

    // 1) scores+copy || w1^T || w2^T, one wave-parallel launch
    prepass_kernel<<<10240, 256>>>(x, gw, w1, w2, out);
    // 2) per-batch top-K (radix select)
    topk_select_kernel<<<BB, 1024>>>();
    // 3) gather selected rows -> fp16 A
    gather_h_kernel<<<MM, 256>>>(x);
    // 4) GEMM1: g_a[8192,1024] @ w1 -> g_h[8192,4096]  (gelu fused, fp16 out)
    mma_gemm<0><<<dim3(DFFN / 128, MM / 256), 256, GSMEM_SZ>>>(b1, nullptr, nullptr);
    // 5) GEMM2: g_h @ w2 + residual -> scattered into out
    mma_gemm<1><<<dim3(DD / 128, MM / 256), 256, GSMEM_SZ>>>(b2, x, out);
}

// round 11
// speedup vs baseline: 1.0607x; 1.0199x over previous
#include <cuda_runtime.h>
#include <cuda_fp16.h>
#include <cstdint>
#include <math.h>

// Problem constants (MoDRouter_48387101556956: fixed shapes)
#define BB   4
#define NN   4096
#define DD   1024
#define DFFN 4096
#define KK   2048
#define MM   (BB * KK)   // 8192 selected tokens total

// ---------------------------------------------------------------------------
// Device scratch
// ---------------------------------------------------------------------------
__device__ float  g_scores[BB * NN];
__device__ int    g_sel[MM];                       // selected token idx per (b,j)
__device__ __half g_a[(size_t)MM * DD];            // gathered fp16 A (16 MB)
__device__ __half g_w1t[(size_t)DFFN * DD];        // w1^T (n-major, K contig), fp16
__device__ __half g_w2t[(size_t)DD * DFFN];        // w2^T (n-major, K contig), fp16
__device__ __half g_h[(size_t)MM * DFFN];          // gelu(x@w1+b1), fp16 (64 MB)

// ---------------------------------------------------------------------------
// Helpers
// ---------------------------------------------------------------------------
__device__ __forceinline__ uint32_t smem_u32(const void* p) {
    uint32_t a;
    asm("{ .reg .u64 t; cvta.to.shared.u64 t, %1; cvt.u32.u64 %0, t; }" : "=r"(a) : "l"(p));
    return a;
}
// gelu-tanh with HW MUFU tanh (sm_75+): |err| <= ~2^-11, inside error budget
__device__ __forceinline__ float gelu_fast(float u) {
    float arg = 0.7978845608028654f * (u + 0.044715f * u * u * u);
    float t;
    asm("tanh.approx.f32 %0, %1;" : "=f"(t) : "f"(arg));
    return 0.5f * u * (1.0f + t);
}

#define CP_ASYNC16(dst, src) \
    asm volatile("cp.async.cg.shared.global [%0], [%1], 16;" :: "r"(dst), "l"(src) : "memory")
#define CP_COMMIT() asm volatile("cp.async.commit_group;" ::: "memory")
#define CP_WAIT1()  asm volatile("cp.async.wait_group 1;" ::: "memory")

// m16n8k16 row.col fp16 MMA, fp32 accumulate (base-ISA, legal on sm_103)
#define MMA_F16(c, a, b0, b1)                                                         \
    asm volatile("mma.sync.aligned.m16n8k16.row.col.f32.f16.f16.f32 "                 \
                 "{%0,%1,%2,%3}, {%4,%5,%6,%7}, {%8,%9}, {%0,%1,%2,%3};"              \
                 : "+f"((c)[0]), "+f"((c)[1]), "+f"((c)[2]), "+f"((c)[3])             \
                 : "r"((a)[0]), "r"((a)[1]), "r"((a)[2]), "r"((a)[3]), "r"(b0), "r"(b1))

// ldmatrix 4x m8n8 b16 (non-transposed)
#define LDSM_X4(r0, r1, r2, r3, addr)                                                 \
    asm volatile("ldmatrix.sync.aligned.m8n8.x4.shared.b16 {%0,%1,%2,%3}, [%4];"      \
                 : "=r"(r0), "=r"(r1), "=r"(r2), "=r"(r3) : "r"(addr))

// ---------------------------------------------------------------------------
// 1) FUSED prepass: scores+copy (CTAs [0,2048)), w1^T (CTAs [2048,6144)),
//    w2^T (CTAs [6144,10240)) — all independent, one wave-parallel launch.
// ---------------------------------------------------------------------------
__device__ __forceinline__ void transpose_body(const float* __restrict__ src,
                                               __half* __restrict__ dst,
                                               int R, int C, int bx, int by,
                                               int tx, int ty, float (*t)[33]) {
#pragma unroll
    for (int i = 0; i < 32; i += 8)
        t[ty + i][tx] = src[(size_t)(by + ty + i) * C + bx + tx];
    __syncthreads();
#pragma unroll
    for (int i = 0; i < 32; i += 8)
        dst[(size_t)(bx + ty + i) * R + by + tx] = __float2half_rn(t[tx][ty + i]);
}

__global__ void prepass_kernel(const float* __restrict__ x,
                               const float* __restrict__ gw,
                               const float* __restrict__ w1,
                               const float* __restrict__ w2,
                               float* __restrict__ out) {
    __shared__ float t[32][33];
    int bid = blockIdx.x, tid = threadIdx.x;
    if (bid < 2048) {
        int gwarp = bid * 8 + (tid >> 5);
        int lane  = tid & 31;
        const float4* xr = reinterpret_cast<const float4*>(x + (size_t)gwarp * DD);
        float4*       orow = reinterpret_cast<float4*>(out + (size_t)gwarp * DD);
        const float4* g4 = reinterpret_cast<const float4*>(gw);
        float s = 0.0f;
#pragma unroll
        for (int i = 0; i < DD / 4 / 32; ++i) {
            float4 a = xr[lane + i * 32];
            float4 b = g4[lane + i * 32];
            orow[lane + i * 32] = a;
            s += a.x * b.x + a.y * b.y + a.z * b.z + a.w * b.w;
        }
#pragma unroll
        for (int o = 16; o; o >>= 1) s += __shfl_xor_sync(0xFFFFFFFFu, s, o);
        if (lane == 0) g_scores[gwarp] = s;
    } else if (bid < 2048 + 4096) {
        int r = bid - 2048;
        int bx = (r & 127) * 32, by = (r >> 7) * 32;
        transpose_body(w1, g_w1t, DD, DFFN, bx, by, tid & 31, tid >> 5, t);
    } else {
        int r = bid - 6144;
        int bx = (r & 31) * 32, by = (r >> 5) * 32;
        transpose_body(w2, g_w2t, DFFN, DD, bx, by, tid & 31, tid >> 5, t);
    }
}

// ---------------------------------------------------------------------------
// 2) Per-batch exact top-K via byte-wise radix select (1 CTA per batch).
// ---------------------------------------------------------------------------
__global__ void topk_select_kernel() {
    __shared__ uint32_t keys[NN];
    __shared__ int      eqidx[NN];
    __shared__ int      hist[256];
    __shared__ int      sh_boundary, sh_remaining, sh_outcnt, sh_eqn;
    __shared__ uint32_t sh_prefix;
    int b = blockIdx.x, tid = threadIdx.x, nthr = blockDim.x;

    for (int i = tid; i < NN; i += nthr) {
        uint32_t u = __float_as_uint(g_scores[b * NN + i]);
        u = (u & 0x80000000u) ? ~u : (u | 0x80000000u);   // monotone map
        keys[i] = u;
    }
    if (tid == 0) { sh_remaining = KK; sh_prefix = 0u; sh_outcnt = 0; }
    __syncthreads();

    for (int byte = 3; byte >= 0; --byte) {
        if (tid < 256) hist[tid] = 0;
        __syncthreads();
        int shift = byte * 8;
        uint32_t pfx = sh_prefix;
        for (int i = tid; i < NN; i += nthr) {
            uint32_t u = keys[i];
            bool active = (byte == 3) || ((u >> (shift + 8)) == pfx);
            if (active) atomicAdd(&hist[(u >> shift) & 0xFF], 1);
        }
        __syncthreads();
        if (tid == 0) {
            int R = sh_remaining, cum = 0, v = 255;
            for (; v > 0; --v) {
                if (cum + hist[v] >= R) break;
                cum += hist[v];
            }
            sh_boundary  = v;
            sh_remaining = R - cum;
            sh_prefix    = (pfx << 8) | (uint32_t)v;
        }
        __syncthreads();
        int bnd = sh_boundary;
        for (int i = tid; i < NN; i += nthr) {
            uint32_t u = keys[i];
            bool active = (byte == 3) || ((u >> (shift + 8)) == pfx);
            if (active && (int)((u >> shift) & 0xFF) > bnd) {
                int slot = atomicAdd(&sh_outcnt, 1);
                g_sel[b * KK + slot] = i;
            }
        }
        __syncthreads();
    }

    if (tid == 0) sh_eqn = 0;
    __syncthreads();
    uint32_t T = sh_prefix;
    for (int i = tid; i < NN; i += nthr)
        if (keys[i] == T) eqidx[atomicAdd(&sh_eqn, 1)] = i;
    __syncthreads();
    int R = sh_remaining, en = sh_eqn;
    for (int j = tid; j < en; j += nthr) {
        int idx = eqidx[j], rank = 0;
        for (int t = 0; t < en; ++t) rank += (eqidx[t] < idx);
        if (rank < R) {
            int slot = atomicAdd(&sh_outcnt, 1);
            g_sel[b * KK + slot] = idx;
        }
    }
}

// ---------------------------------------------------------------------------
// 3) Gather selected rows + convert fp16 -> g_a
// ---------------------------------------------------------------------------
__global__ void gather_h_kernel(const float* __restrict__ x) {
    int m = blockIdx.x;
    int c = threadIdx.x;
    int tok = g_sel[m];
    size_t src = ((size_t)(m >> 11) * NN + tok) * DD + c * 4;
    float4 v = *reinterpret_cast<const float4*>(x + src);
    __half2 h0 = __floats2half2_rn(v.x, v.y);
    __half2 h1 = __floats2half2_rn(v.z, v.w);
    uint2 pk;
    pk.x = *reinterpret_cast<uint32_t*>(&h0);
    pk.y = *reinterpret_cast<uint32_t*>(&h1);
    *reinterpret_cast<uint2*>(g_a + (size_t)m * DD + c * 4) = pk;
}

// ---------------------------------------------------------------------------
// fp16 mma.sync GEMM, CTA tile 128x128, 128 threads = 4 warps (2M x 2N),
// warp tile 64x64. __launch_bounds__(128,2) -> 2 CTAs/SM: independent barrier
// groups cover each other's sync/cp.async stalls (tensor was 47.7% with one
// 256-thr CTA/SM). Fragment ks-loop double-buffered to hide LDSM->MMA latency.
//   MODE 0: ffn1  A=g_a (K=1024), B=g_w1t  ->  g_h = h(gelu(C + b1))
//   MODE 1: ffn2  A=g_h (K=4096), B=g_w2t  ->  out[sel] = x[sel] + C + b2
// BK=64, 3-stage cp.async pipeline, ONE __syncthreads per K-iter.
// Row pitch 144B keeps ldmatrix phases conflict-free.
// ---------------------------------------------------------------------------
#define HPITCH_B 144                               // bytes per row (72 halves)
#define A_STG (128 * HPITCH_B)                     // 18432 B
#define B_STG (128 * HPITCH_B)                     // 18432 B
#define NSTG 3
#define GSMEM_SZ (NSTG * (A_STG + B_STG))          // 110592 B per CTA

__device__ __forceinline__ void ld_stage(uint32_t sb, int stage,
                                         const __half* __restrict__ A,
                                         const __half* __restrict__ Bw,
                                         int Kdim, int mt, int nt, int k0, int tid) {
    uint32_t abase = sb + stage * A_STG;
    uint32_t bbase = sb + NSTG * A_STG + stage * B_STG;
    // 128 rows x 8 chunks = 1024 slots, 128 threads -> 8 per thread (each matrix)
#pragma unroll
    for (int i = 0; i < 8; ++i) {
        int lin = i * 128 + tid;
        int row = lin >> 3, ch = lin & 7;
        CP_ASYNC16(abase + row * HPITCH_B + ch * 16,
                   A + (size_t)(mt * 128 + row) * Kdim + k0 + ch * 8);
    }
#pragma unroll
    for (int i = 0; i < 8; ++i) {
        int lin = i * 128 + tid;
        int row = lin >> 3, ch = lin & 7;
        CP_ASYNC16(bbase + row * HPITCH_B + ch * 16,
                   Bw + (size_t)(nt * 128 + row) * Kdim + k0 + ch * 8);
    }
}

template <int MODE>
__global__ __launch_bounds__(128, 2)
void mma_gemm(const float* __restrict__ bias,
              const float* __restrict__ xin,
              float* __restrict__ outp) {
    extern __shared__ uint32_t smw[];
    const __half* A    = (MODE == 0) ? g_a   : g_h;
    const __half* Bw   = (MODE == 0) ? g_w1t : g_w2t;
    const int     Kdim = (MODE == 0) ? DD : DFFN;
    const int     KT   = Kdim / 64;

    int tid = threadIdx.x, lane = tid & 31, wid = tid >> 5;
    int wm = wid >> 1, wn = wid & 1;               // warp tile: rows wm*64, cols wn*64
    int mt = blockIdx.y, nt = blockIdx.x;
    uint32_t sb = smem_u32(smw);

    // ldmatrix lane offsets: matrices {r0-7,k0-7},{r8-15,k0-7},{r0-7,k8-15},{r8-15,k8-15}
    int lrow = ((lane >> 3) & 1) * 8 + (lane & 7);
    int koff = (lane >= 16) ? 16 : 0;
    uint32_t a_off[4], b_off[4];
#pragma unroll
    for (int mi = 0; mi < 4; ++mi)
        a_off[mi] = (wm * 64 + mi * 16 + lrow) * HPITCH_B + koff;
#pragma unroll
    for (int p = 0; p < 4; ++p)
        b_off[p] = (wn * 64 + p * 16 + lrow) * HPITCH_B + koff;

    float acc[4][8][4];
#pragma unroll
    for (int mi = 0; mi < 4; ++mi)
#pragma unroll
        for (int ni = 0; ni < 8; ++ni)
#pragma unroll
            for (int q = 0; q < 4; ++q) acc[mi][ni][q] = 0.0f;

    ld_stage(sb, 0, A, Bw, Kdim, mt, nt, 0, tid);
    CP_COMMIT();
    ld_stage(sb, 1, A, Bw, Kdim, mt, nt, 64, tid);
    CP_COMMIT();

    uint32_t af[2][4][4], bf[2][4][4];             // ks-level double-buffered frags
    int stage = 0;
    for (int k = 0; k < KT; ++k) {
        CP_WAIT1();
        __syncthreads();

        int pstage = stage + 2 >= NSTG ? stage + 2 - NSTG : stage + 2;
        if (k + 2 < KT)
            ld_stage(sb, pstage, A, Bw, Kdim, mt, nt, (k + 2) * 64, tid);
        CP_COMMIT();

        uint32_t As_addr = sb + stage * A_STG;
        uint32_t Bs_addr = sb + NSTG * A_STG + stage * B_STG;

        // prime frags for ks=0
#pragma unroll
        for (int mi = 0; mi < 4; ++mi)
            LDSM_X4(af[0][mi][0], af[0][mi][1], af[0][mi][2], af[0][mi][3],
                    As_addr + a_off[mi]);
#pragma unroll
        for (int p = 0; p < 4; ++p)
            LDSM_X4(bf[0][p][0], bf[0][p][1], bf[0][p][2], bf[0][p][3],
                    Bs_addr + b_off[p]);

#pragma unroll
        for (int ks = 0; ks < 4; ++ks) {
            int cur = ks & 1, nxt = cur ^ 1;
            if (ks < 3) {                           // prefetch next ks frags
#pragma unroll
                for (int mi = 0; mi < 4; ++mi)
                    LDSM_X4(af[nxt][mi][0], af[nxt][mi][1], af[nxt][mi][2], af[nxt][mi][3],
                            As_addr + a_off[mi] + (ks + 1) * 32);
#pragma unroll
                for (int p = 0; p < 4; ++p)
                    LDSM_X4(bf[nxt][p][0], bf[nxt][p][1], bf[nxt][p][2], bf[nxt][p][3],
                            Bs_addr + b_off[p] + (ks + 1) * 32);
            }
#pragma unroll
            for (int p = 0; p < 4; ++p) {
#pragma unroll
                for (int mi = 0; mi < 4; ++mi) {
                    MMA_F16(acc[mi][2 * p + 0], af[cur][mi], bf[cur][p][0], bf[cur][p][2]);
                    MMA_F16(acc[mi][2 * p + 1], af[cur][mi], bf[cur][p][1], bf[cur][p][3]);
                }
            }
        }
        stage = stage + 1 == NSTG ? 0 : stage + 1;
    }

    // ---------------- Epilogue ----------------
    int r = lane >> 2, c = lane & 3;
    if (MODE == 0) {
#pragma unroll
        for (int mi = 0; mi < 4; ++mi) {
#pragma unroll
            for (int half = 0; half < 2; ++half) {
                int m = mt * 128 + wm * 64 + mi * 16 + half * 8 + r;
                __half* hrow = g_h + (size_t)m * DFFN;
#pragma unroll
                for (int ni = 0; ni < 8; ++ni) {
                    int n = nt * 128 + wn * 64 + ni * 8 + c * 2;
                    float v0 = gelu_fast(acc[mi][ni][half * 2 + 0] + bias[n]);
                    float v1 = gelu_fast(acc[mi][ni][half * 2 + 1] + bias[n + 1]);
                    __half2 hv = __floats2half2_rn(v0, v1);
                    *reinterpret_cast<__half2*>(hrow + n) = hv;
                }
            }
        }
    } else {
#pragma unroll
        for (int mi = 0; mi < 4; ++mi) {
#pragma unroll
            for (int half = 0; half < 2; ++half) {
                int m = mt * 128 + wm * 64 + mi * 16 + half * 8 + r;
                int tok = g_sel[m];
                size_t base = ((size_t)(m >> 11) * NN + tok) * DD;
#pragma unroll
                for (int ni = 0; ni < 8; ++ni) {
                    int n = nt * 128 + wn * 64 + ni * 8 + c * 2;
                    float2 xv = *reinterpret_cast<const float2*>(xin + base + n);
                    float2 w;
                    w.x = xv.x + acc[mi][ni][half * 2 + 0] + bias[n];
                    w.y = xv.y + acc[mi][ni][half * 2 + 1] + bias[n + 1];
                    *reinterpret_cast<float2*>(outp + base + n) = w;
                }
            }
        }
    }
}

// ---------------------------------------------------------------------------
// Launch: x, gate_w, w1, b1, w2, b2, k
// ---------------------------------------------------------------------------
extern "C" void kernel_launch(void* const* d_in, const int* in_sizes, int n_in,
                              void* d_out, int out_size) {
    const float* x  = (const float*)d_in[0];
    const float* gw = (const float*)d_in[1];
    const float* w1 = (const float*)d_in[2];
    const float* b1 = (const float*)d_in[3];
    const float* w2 = (const float*)d_in[4];
    const float* b2 = (const float*)d_in[5];
    float* out = (float*)d_out;

    cudaFuncSetAttribute(mma_gemm<0>, cudaFuncAttributeMaxDynamicSharedMemorySize, GSMEM_SZ);
    cudaFuncSetAttribute(mma_gemm<1>, cudaFuncAttributeMaxDynamicSharedMemorySize, GSMEM_SZ);

    // 1) scores+copy || w1^T || w2^T, one wave-parallel launch
    prepass_kernel<<<10240, 256>>>(x, gw, w1, w2, out);
    // 2) per-batch top-K (radix select)
    topk_select_kernel<<<BB, 1024>>>();
    // 3) gather selected rows -> fp16 A
    gather_h_kernel<<<MM, 256>>>(x);
    // 4) GEMM1: g_a[8192,1024] @ w1 -> g_h[8192,4096]  (gelu fused, fp16 out)
    mma_gemm<0><<<dim3(DFFN / 128, MM / 128), 128, GSMEM_SZ>>>(b1, nullptr, nullptr);
    // 5) GEMM2: g_h @ w2 + residual -> scattered into out
    mma_gemm<1><<<dim3(DD / 128, MM / 128), 128, GSMEM_SZ>>>(b2, x, out);
}

// round 12
// speedup vs baseline: 1.0853x; 1.0231x over previous
#include <cuda_runtime.h>
#include <cuda_fp16.h>
#include <cstdint>
#include <math.h>

// Problem constants (MoDRouter_48387101556956: fixed shapes)
#define BB   4
#define NN   4096
#define DD   1024
#define DFFN 4096
#define KK   2048
#define MM   (BB * KK)   // 8192 selected tokens total

// ---------------------------------------------------------------------------
// Device scratch
// ---------------------------------------------------------------------------
__device__ float  g_scores[BB * NN];
__device__ int    g_sel[MM];                       // selected token idx per (b,j)
__device__ __half g_a[(size_t)MM * DD];            // gathered fp16 A (16 MB)
__device__ __half g_w1t[(size_t)DFFN * DD];        // w1^T (n-major, K contig), fp16
__device__ __half g_w2t[(size_t)DD * DFFN];        // w2^T (n-major, K contig), fp16
__device__ __half g_h[(size_t)MM * DFFN];          // gelu(x@w1+b1), fp16 (64 MB)

// ---------------------------------------------------------------------------
// Helpers
// ---------------------------------------------------------------------------
__device__ __forceinline__ uint32_t smem_u32(const void* p) {
    uint32_t a;
    asm("{ .reg .u64 t; cvta.to.shared.u64 t, %1; cvt.u32.u64 %0, t; }" : "=r"(a) : "l"(p));
    return a;
}
// gelu-tanh with HW MUFU tanh (sm_75+): |err| <= ~2^-11, inside error budget
__device__ __forceinline__ float gelu_fast(float u) {
    float arg = 0.7978845608028654f * (u + 0.044715f * u * u * u);
    float t;
    asm("tanh.approx.f32 %0, %1;" : "=f"(t) : "f"(arg));
    return 0.5f * u * (1.0f + t);
}

#define CP_ASYNC16(dst, src) \
    asm volatile("cp.async.cg.shared.global [%0], [%1], 16;" :: "r"(dst), "l"(src) : "memory")
#define CP_COMMIT() asm volatile("cp.async.commit_group;" ::: "memory")
#define CP_WAIT1()  asm volatile("cp.async.wait_group 1;" ::: "memory")

// m16n8k16 row.col fp16 MMA, fp32 accumulate (base-ISA, legal on sm_103)
#define MMA_F16(c, a, b0, b1)                                                         \
    asm volatile("mma.sync.aligned.m16n8k16.row.col.f32.f16.f16.f32 "                 \
                 "{%0,%1,%2,%3}, {%4,%5,%6,%7}, {%8,%9}, {%0,%1,%2,%3};"              \
                 : "+f"((c)[0]), "+f"((c)[1]), "+f"((c)[2]), "+f"((c)[3])             \
                 : "r"((a)[0]), "r"((a)[1]), "r"((a)[2]), "r"((a)[3]), "r"(b0), "r"(b1))

// ldmatrix 4x m8n8 b16 (non-transposed)
#define LDSM_X4(r0, r1, r2, r3, addr)                                                 \
    asm volatile("ldmatrix.sync.aligned.m8n8.x4.shared.b16 {%0,%1,%2,%3}, [%4];"      \
                 : "=r"(r0), "=r"(r1), "=r"(r2), "=r"(r3) : "r"(addr))

// ---------------------------------------------------------------------------
// 1) FUSED prepass: scores+copy (CTAs [0,2048)), w1^T (CTAs [2048,6144)),
//    w2^T (CTAs [6144,10240)) — all independent, one wave-parallel launch.
// ---------------------------------------------------------------------------
__device__ __forceinline__ void transpose_body(const float* __restrict__ src,
                                               __half* __restrict__ dst,
                                               int R, int C, int bx, int by,
                                               int tx, int ty, float (*t)[33]) {
#pragma unroll
    for (int i = 0; i < 32; i += 8)
        t[ty + i][tx] = src[(size_t)(by + ty + i) * C + bx + tx];
    __syncthreads();
#pragma unroll
    for (int i = 0; i < 32; i += 8)
        dst[(size_t)(bx + ty + i) * R + by + tx] = __float2half_rn(t[tx][ty + i]);
}

__global__ void prepass_kernel(const float* __restrict__ x,
                               const float* __restrict__ gw,
                               const float* __restrict__ w1,
                               const float* __restrict__ w2,
                               float* __restrict__ out) {
    __shared__ float t[32][33];
    int bid = blockIdx.x, tid = threadIdx.x;
    if (bid < 2048) {
        int gwarp = bid * 8 + (tid >> 5);
        int lane  = tid & 31;
        const float4* xr = reinterpret_cast<const float4*>(x + (size_t)gwarp * DD);
        float4*       orow = reinterpret_cast<float4*>(out + (size_t)gwarp * DD);
        const float4* g4 = reinterpret_cast<const float4*>(gw);
        float s = 0.0f;
#pragma unroll
        for (int i = 0; i < DD / 4 / 32; ++i) {
            float4 a = xr[lane + i * 32];
            float4 b = g4[lane + i * 32];
            orow[lane + i * 32] = a;
            s += a.x * b.x + a.y * b.y + a.z * b.z + a.w * b.w;
        }
#pragma unroll
        for (int o = 16; o; o >>= 1) s += __shfl_xor_sync(0xFFFFFFFFu, s, o);
        if (lane == 0) g_scores[gwarp] = s;
    } else if (bid < 2048 + 4096) {
        int r = bid - 2048;
        int bx = (r & 127) * 32, by = (r >> 7) * 32;
        transpose_body(w1, g_w1t, DD, DFFN, bx, by, tid & 31, tid >> 5, t);
    } else {
        int r = bid - 6144;
        int bx = (r & 31) * 32, by = (r >> 5) * 32;
        transpose_body(w2, g_w2t, DFFN, DD, bx, by, tid & 31, tid >> 5, t);
    }
}

// ---------------------------------------------------------------------------
// 2) Per-batch exact top-K via byte-wise radix select (1 CTA per batch).
// ---------------------------------------------------------------------------
__global__ void topk_select_kernel() {
    __shared__ uint32_t keys[NN];
    __shared__ int      eqidx[NN];
    __shared__ int      hist[256];
    __shared__ int      sh_boundary, sh_remaining, sh_outcnt, sh_eqn;
    __shared__ uint32_t sh_prefix;
    int b = blockIdx.x, tid = threadIdx.x, nthr = blockDim.x;

    for (int i = tid; i < NN; i += nthr) {
        uint32_t u = __float_as_uint(g_scores[b * NN + i]);
        u = (u & 0x80000000u) ? ~u : (u | 0x80000000u);   // monotone map
        keys[i] = u;
    }
    if (tid == 0) { sh_remaining = KK; sh_prefix = 0u; sh_outcnt = 0; }
    __syncthreads();

    for (int byte = 3; byte >= 0; --byte) {
        if (tid < 256) hist[tid] = 0;
        __syncthreads();
        int shift = byte * 8;
        uint32_t pfx = sh_prefix;
        for (int i = tid; i < NN; i += nthr) {
            uint32_t u = keys[i];
            bool active = (byte == 3) || ((u >> (shift + 8)) == pfx);
            if (active) atomicAdd(&hist[(u >> shift) & 0xFF], 1);
        }
        __syncthreads();
        if (tid == 0) {
            int R = sh_remaining, cum = 0, v = 255;
            for (; v > 0; --v) {
                if (cum + hist[v] >= R) break;
                cum += hist[v];
            }
            sh_boundary  = v;
            sh_remaining = R - cum;
            sh_prefix    = (pfx << 8) | (uint32_t)v;
        }
        __syncthreads();
        int bnd = sh_boundary;
        for (int i = tid; i < NN; i += nthr) {
            uint32_t u = keys[i];
            bool active = (byte == 3) || ((u >> (shift + 8)) == pfx);
            if (active && (int)((u >> shift) & 0xFF) > bnd) {
                int slot = atomicAdd(&sh_outcnt, 1);
                g_sel[b * KK + slot] = i;
            }
        }
        __syncthreads();
    }

    if (tid == 0) sh_eqn = 0;
    __syncthreads();
    uint32_t T = sh_prefix;
    for (int i = tid; i < NN; i += nthr)
        if (keys[i] == T) eqidx[atomicAdd(&sh_eqn, 1)] = i;
    __syncthreads();
    int R = sh_remaining, en = sh_eqn;
    for (int j = tid; j < en; j += nthr) {
        int idx = eqidx[j], rank = 0;
        for (int t = 0; t < en; ++t) rank += (eqidx[t] < idx);
        if (rank < R) {
            int slot = atomicAdd(&sh_outcnt, 1);
            g_sel[b * KK + slot] = idx;
        }
    }
}

// ---------------------------------------------------------------------------
// 3) Gather selected rows + convert fp16 -> g_a
// ---------------------------------------------------------------------------
__global__ void gather_h_kernel(const float* __restrict__ x) {
    int m = blockIdx.x;
    int c = threadIdx.x;
    int tok = g_sel[m];
    size_t src = ((size_t)(m >> 11) * NN + tok) * DD + c * 4;
    float4 v = *reinterpret_cast<const float4*>(x + src);
    __half2 h0 = __floats2half2_rn(v.x, v.y);
    __half2 h1 = __floats2half2_rn(v.z, v.w);
    uint2 pk;
    pk.x = *reinterpret_cast<uint32_t*>(&h0);
    pk.y = *reinterpret_cast<uint32_t*>(&h1);
    *reinterpret_cast<uint2*>(g_a + (size_t)m * DD + c * 4) = pk;
}

// ---------------------------------------------------------------------------
// fp16 mma.sync GEMM, CTA tile 128x128, 256 threads = 8 warps (4M x 2N),
// warp tile 32x64 (acc 64 regs). __launch_bounds__(256,2) -> 2 CTAs/SM
// = 16 warps/SM = 4 warps/SMSP: doubles stall coverage at the 50%-idle
// tensor pipe seen with 2 warps/SMSP (R8/R9 both pinned at ~48-50%).
//   MODE 0: ffn1  A=g_a (K=1024), B=g_w1t  ->  g_h = h(gelu(C + b1))
//   MODE 1: ffn2  A=g_h (K=4096), B=g_w2t  ->  out[sel] = x[sel] + C + b2
// BK=64, 3-stage cp.async pipeline, ONE __syncthreads per K-iter.
// Row pitch 144B keeps ldmatrix phases conflict-free.
// ---------------------------------------------------------------------------
#define HPITCH_B 144                               // bytes per row (72 halves)
#define A_STG (128 * HPITCH_B)                     // 18432 B
#define B_STG (128 * HPITCH_B)                     // 18432 B
#define NSTG 3
#define GSMEM_SZ (NSTG * (A_STG + B_STG))          // 110592 B per CTA

__device__ __forceinline__ void ld_stage(uint32_t sb, int stage,
                                         const __half* __restrict__ A,
                                         const __half* __restrict__ Bw,
                                         int Kdim, int mt, int nt, int k0, int tid) {
    uint32_t abase = sb + stage * A_STG;
    uint32_t bbase = sb + NSTG * A_STG + stage * B_STG;
    // 128 rows x 8 chunks = 1024 slots, 256 threads -> 4 per thread (each matrix)
#pragma unroll
    for (int i = 0; i < 4; ++i) {
        int lin = i * 256 + tid;
        int row = lin >> 3, ch = lin & 7;
        CP_ASYNC16(abase + row * HPITCH_B + ch * 16,
                   A + (size_t)(mt * 128 + row) * Kdim + k0 + ch * 8);
    }
#pragma unroll
    for (int i = 0; i < 4; ++i) {
        int lin = i * 256 + tid;
        int row = lin >> 3, ch = lin & 7;
        CP_ASYNC16(bbase + row * HPITCH_B + ch * 16,
                   Bw + (size_t)(nt * 128 + row) * Kdim + k0 + ch * 8);
    }
}

template <int MODE>
__global__ __launch_bounds__(256, 2)
void mma_gemm(const float* __restrict__ bias,
              const float* __restrict__ xin,
              float* __restrict__ outp) {
    extern __shared__ uint32_t smw[];
    const __half* A    = (MODE == 0) ? g_a   : g_h;
    const __half* Bw   = (MODE == 0) ? g_w1t : g_w2t;
    const int     Kdim = (MODE == 0) ? DD : DFFN;
    const int     KT   = Kdim / 64;

    int tid = threadIdx.x, lane = tid & 31, wid = tid >> 5;
    int wm = wid >> 1, wn = wid & 1;               // warp tile: rows wm*32, cols wn*64
    int mt = blockIdx.y, nt = blockIdx.x;
    uint32_t sb = smem_u32(smw);

    // ldmatrix lane offsets: matrices {r0-7,k0-7},{r8-15,k0-7},{r0-7,k8-15},{r8-15,k8-15}
    int lrow = ((lane >> 3) & 1) * 8 + (lane & 7);
    int koff = (lane >= 16) ? 16 : 0;
    uint32_t a_off[2], b_off[4];
#pragma unroll
    for (int mi = 0; mi < 2; ++mi)
        a_off[mi] = (wm * 32 + mi * 16 + lrow) * HPITCH_B + koff;
#pragma unroll
    for (int p = 0; p < 4; ++p)
        b_off[p] = (wn * 64 + p * 16 + lrow) * HPITCH_B + koff;

    float acc[2][8][4];
#pragma unroll
    for (int mi = 0; mi < 2; ++mi)
#pragma unroll
        for (int ni = 0; ni < 8; ++ni)
#pragma unroll
            for (int q = 0; q < 4; ++q) acc[mi][ni][q] = 0.0f;

    ld_stage(sb, 0, A, Bw, Kdim, mt, nt, 0, tid);
    CP_COMMIT();
    ld_stage(sb, 1, A, Bw, Kdim, mt, nt, 64, tid);
    CP_COMMIT();

    int stage = 0;
    for (int k = 0; k < KT; ++k) {
        CP_WAIT1();
        __syncthreads();

        int pstage = stage + 2 >= NSTG ? stage + 2 - NSTG : stage + 2;
        if (k + 2 < KT)
            ld_stage(sb, pstage, A, Bw, Kdim, mt, nt, (k + 2) * 64, tid);
        CP_COMMIT();

        uint32_t As_addr = sb + stage * A_STG;
        uint32_t Bs_addr = sb + NSTG * A_STG + stage * B_STG;
#pragma unroll
        for (int ks = 0; ks < 4; ++ks) {           // 4 x K=16
            uint32_t a[2][4];
#pragma unroll
            for (int mi = 0; mi < 2; ++mi)
                LDSM_X4(a[mi][0], a[mi][1], a[mi][2], a[mi][3],
                        As_addr + a_off[mi] + ks * 32);
#pragma unroll
            for (int p = 0; p < 4; ++p) {
                uint32_t b0, b1, b2, b3;           // (ni0.k0, ni1.k0, ni0.k8, ni1.k8)
                LDSM_X4(b0, b1, b2, b3, Bs_addr + b_off[p] + ks * 32);
#pragma unroll
                for (int mi = 0; mi < 2; ++mi) {
                    MMA_F16(acc[mi][2 * p + 0], a[mi], b0, b2);
                    MMA_F16(acc[mi][2 * p + 1], a[mi], b1, b3);
                }
            }
        }
        stage = stage + 1 == NSTG ? 0 : stage + 1;
    }

    // ---------------- Epilogue ----------------
    int r = lane >> 2, c = lane & 3;
    if (MODE == 0) {
#pragma unroll
        for (int mi = 0; mi < 2; ++mi) {
#pragma unroll
            for (int half = 0; half < 2; ++half) {
                int m = mt * 128 + wm * 32 + mi * 16 + half * 8 + r;
                __half* hrow = g_h + (size_t)m * DFFN;
#pragma unroll
                for (int ni = 0; ni < 8; ++ni) {
                    int n = nt * 128 + wn * 64 + ni * 8 + c * 2;
                    float v0 = gelu_fast(acc[mi][ni][half * 2 + 0] + bias[n]);
                    float v1 = gelu_fast(acc[mi][ni][half * 2 + 1] + bias[n + 1]);
                    __half2 hv = __floats2half2_rn(v0, v1);
                    *reinterpret_cast<__half2*>(hrow + n) = hv;
                }
            }
        }
    } else {
#pragma unroll
        for (int mi = 0; mi < 2; ++mi) {
#pragma unroll
            for (int half = 0; half < 2; ++half) {
                int m = mt * 128 + wm * 32 + mi * 16 + half * 8 + r;
                int tok = g_sel[m];
                size_t base = ((size_t)(m >> 11) * NN + tok) * DD;
#pragma unroll
                for (int ni = 0; ni < 8; ++ni) {
                    int n = nt * 128 + wn * 64 + ni * 8 + c * 2;
                    float2 xv = *reinterpret_cast<const float2*>(xin + base + n);
                    float2 w;
                    w.x = xv.x + acc[mi][ni][half * 2 + 0] + bias[n];
                    w.y = xv.y + acc[mi][ni][half * 2 + 1] + bias[n + 1];
                    *reinterpret_cast<float2*>(outp + base + n) = w;
                }
            }
        }
    }
}

// ---------------------------------------------------------------------------
// Launch: x, gate_w, w1, b1, w2, b2, k
// ---------------------------------------------------------------------------
extern "C" void kernel_launch(void* const* d_in, const int* in_sizes, int n_in,
                              void* d_out, int out_size) {
    const float* x  = (const float*)d_in[0];
    const float* gw = (const float*)d_in[1];
    const float* w1 = (const float*)d_in[2];
    const float* b1 = (const float*)d_in[3];
    const float* w2 = (const float*)d_in[4];
    const float* b2 = (const float*)d_in[5];
    float* out = (float*)d_out;

    cudaFuncSetAttribute(mma_gemm<0>, cudaFuncAttributeMaxDynamicSharedMemorySize, GSMEM_SZ);
    cudaFuncSetAttribute(mma_gemm<1>, cudaFuncAttributeMaxDynamicSharedMemorySize, GSMEM_SZ);

    // 1) scores+copy || w1^T || w2^T, one wave-parallel launch
    prepass_kernel<<<10240, 256>>>(x, gw, w1, w2, out);
    // 2) per-batch top-K (radix select)
    topk_select_kernel<<<BB, 1024>>>();
    // 3) gather selected rows -> fp16 A
    gather_h_kernel<<<MM, 256>>>(x);
    // 4) GEMM1: g_a[8192,1024] @ w1 -> g_h[8192,4096]  (gelu fused, fp16 out)
    mma_gemm<0><<<dim3(DFFN / 128, MM / 128), 256, GSMEM_SZ>>>(b1, nullptr, nullptr);
    // 5) GEMM2: g_h @ w2 + residual -> scattered into out
    mma_gemm<1><<<dim3(DD / 128, MM / 128), 256, GSMEM_SZ>>>(b2, x, out);
}

// round 13
// speedup vs baseline: 1.0947x; 1.0087x over previous
#include <cuda_runtime.h>
#include <cuda_fp16.h>
#include <cstdint>
#include <math.h>

// Problem constants (MoDRouter_48387101556956: fixed shapes)
#define BB   4
#define NN   4096
#define DD   1024
#define DFFN 4096
#define KK   2048
#define MM   (BB * KK)   // 8192 selected tokens total

// ---------------------------------------------------------------------------
// Device scratch
// ---------------------------------------------------------------------------
__device__ float  g_scores[BB * NN];
__device__ int    g_sel[MM];                       // selected token idx per (b,j)
__device__ __half g_a[(size_t)MM * DD];            // gathered fp16 A (16 MB)
__device__ __half g_w1t[(size_t)DFFN * DD];        // w1^T (n-major, K contig), fp16
__device__ __half g_w2t[(size_t)DD * DFFN];        // w2^T (n-major, K contig), fp16
__device__ __half g_h[(size_t)MM * DFFN];          // gelu(x@w1+b1), fp16 (64 MB)

// ---------------------------------------------------------------------------
// Helpers
// ---------------------------------------------------------------------------
__device__ __forceinline__ uint32_t smem_u32(const void* p) {
    uint32_t a;
    asm("{ .reg .u64 t; cvta.to.shared.u64 t, %1; cvt.u32.u64 %0, t; }" : "=r"(a) : "l"(p));
    return a;
}
// gelu-tanh with HW MUFU tanh (sm_75+): |err| <= ~2^-11, inside error budget
__device__ __forceinline__ float gelu_fast(float u) {
    float arg = 0.7978845608028654f * (u + 0.044715f * u * u * u);
    float t;
    asm("tanh.approx.f32 %0, %1;" : "=f"(t) : "f"(arg));
    return 0.5f * u * (1.0f + t);
}

#define CP_ASYNC16(dst, src) \
    asm volatile("cp.async.cg.shared.global [%0], [%1], 16;" :: "r"(dst), "l"(src) : "memory")
#define CP_COMMIT() asm volatile("cp.async.commit_group;" ::: "memory")
#define CP_WAIT1()  asm volatile("cp.async.wait_group 1;" ::: "memory")

// m16n8k16 row.col fp16 MMA, fp32 accumulate (base-ISA, legal on sm_103)
#define MMA_F16(c, a, b0, b1)                                                         \
    asm volatile("mma.sync.aligned.m16n8k16.row.col.f32.f16.f16.f32 "                 \
                 "{%0,%1,%2,%3}, {%4,%5,%6,%7}, {%8,%9}, {%0,%1,%2,%3};"              \
                 : "+f"((c)[0]), "+f"((c)[1]), "+f"((c)[2]), "+f"((c)[3])             \
                 : "r"((a)[0]), "r"((a)[1]), "r"((a)[2]), "r"((a)[3]), "r"(b0), "r"(b1))

// ldmatrix 4x m8n8 b16 (non-transposed)
#define LDSM_X4(r0, r1, r2, r3, addr)                                                 \
    asm volatile("ldmatrix.sync.aligned.m8n8.x4.shared.b16 {%0,%1,%2,%3}, [%4];"      \
                 : "=r"(r0), "=r"(r1), "=r"(r2), "=r"(r3) : "r"(addr))

// ---------------------------------------------------------------------------
// 1) Gate scores + out=x copy fused — one warp per row (reads the row anyway)
// ---------------------------------------------------------------------------
__global__ void scores_copy_kernel(const float* __restrict__ x,
                                   const float* __restrict__ gw,
                                   float* __restrict__ out) {
    int gwarp = (blockIdx.x * blockDim.x + threadIdx.x) >> 5;
    int lane  = threadIdx.x & 31;
    if (gwarp >= BB * NN) return;
    const float4* xr = reinterpret_cast<const float4*>(x + (size_t)gwarp * DD);
    float4*       orow = reinterpret_cast<float4*>(out + (size_t)gwarp * DD);
    const float4* g4 = reinterpret_cast<const float4*>(gw);
    float s = 0.0f;
#pragma unroll
    for (int i = 0; i < DD / 4 / 32; ++i) {
        float4 a = xr[lane + i * 32];
        float4 b = g4[lane + i * 32];
        orow[lane + i * 32] = a;
        s += a.x * b.x + a.y * b.y + a.z * b.z + a.w * b.w;
    }
#pragma unroll
    for (int o = 16; o; o >>= 1) s += __shfl_xor_sync(0xFFFFFFFFu, s, o);
    if (lane == 0) g_scores[gwarp] = s;
}

// ---------------------------------------------------------------------------
// 2) MID kernel: CTAs 0-3 run per-batch exact top-K (radix select) while
//    CTAs 4..2051 transpose w1/w2 to fp16 K-major — topk's latency hides
//    under the transposes' bandwidth work (was serialized on 4 SMs before).
//    1024 threads; transpose CTAs process 4 32x32 tiles (sub = tid>>8).
// ---------------------------------------------------------------------------
#define MID_SMEM 33824   // keys 16K | eqidx 16K | hist 1K | ctrl 32B (transpose reuses)

__global__ void mid_kernel(const float* __restrict__ w1,
                           const float* __restrict__ w2) {
    extern __shared__ char sh[];
    int bid = blockIdx.x, tid = threadIdx.x, nthr = blockDim.x;

    if (bid >= 4) {
        // ---- transpose path: 4 subtiles of 32x32 per CTA ----
        float (*t)[32][33] = reinterpret_cast<float (*)[32][33]>(sh);
        int sub  = tid >> 8;            // 0..3
        int stid = tid & 255;
        int tx = stid & 31, ty = stid >> 5;   // ty 0..7
        const float* src; __half* dst; int R, C, bx, by;
        if (bid < 4 + 1024) {           // w1 [DD, DFFN] -> g_w1t [DFFN, DD]
            int r = (bid - 4) * 4 + sub;
            src = w1; dst = g_w1t; R = DD; C = DFFN;
            bx = (r & 127) * 32; by = (r >> 7) * 32;
        } else {                        // w2 [DFFN, DD] -> g_w2t [DD, DFFN]
            int r = (bid - 4 - 1024) * 4 + sub;
            src = w2; dst = g_w2t; R = DFFN; C = DD;
            bx = (r & 31) * 32; by = (r >> 5) * 32;
        }
#pragma unroll
        for (int i = 0; i < 32; i += 8)
            t[sub][ty + i][tx] = src[(size_t)(by + ty + i) * C + bx + tx];
        __syncthreads();
#pragma unroll
        for (int i = 0; i < 32; i += 8)
            dst[(size_t)(bx + ty + i) * R + by + tx] = __float2half_rn(t[sub][tx][ty + i]);
        return;
    }

    // ---- top-K path (CTAs 0-3, one batch each) ----
    uint32_t* keys  = reinterpret_cast<uint32_t*>(sh);
    int*      eqidx = reinterpret_cast<int*>(sh + 16384);
    int*      hist  = reinterpret_cast<int*>(sh + 32768);
    int*      ctrl  = reinterpret_cast<int*>(sh + 33792);
    // ctrl[0]=boundary ctrl[1]=remaining ctrl[2]=outcnt ctrl[3]=eqn ctrl[4]=prefix
    int b = bid;

    for (int i = tid; i < NN; i += nthr) {
        uint32_t u = __float_as_uint(g_scores[b * NN + i]);
        u = (u & 0x80000000u) ? ~u : (u | 0x80000000u);   // monotone map
        keys[i] = u;
    }
    if (tid == 0) { ctrl[1] = KK; ctrl[2] = 0; ctrl[4] = 0; }
    __syncthreads();

    for (int byte = 3; byte >= 0; --byte) {
        if (tid < 256) hist[tid] = 0;
        __syncthreads();
        int shift = byte * 8;
        uint32_t pfx = (uint32_t)ctrl[4];
        for (int i = tid; i < NN; i += nthr) {
            uint32_t u = keys[i];
            bool active = (byte == 3) || ((u >> (shift + 8)) == pfx);
            if (active) atomicAdd(&hist[(u >> shift) & 0xFF], 1);
        }
        __syncthreads();
        if (tid == 0) {
            int R = ctrl[1], cum = 0, v = 255;
            for (; v > 0; --v) {
                if (cum + hist[v] >= R) break;
                cum += hist[v];
            }
            ctrl[0] = v;
            ctrl[1] = R - cum;
            ctrl[4] = (int)((pfx << 8) | (uint32_t)v);
        }
        __syncthreads();
        int bnd = ctrl[0];
        for (int i = tid; i < NN; i += nthr) {
            uint32_t u = keys[i];
            bool active = (byte == 3) || ((u >> (shift + 8)) == pfx);
            if (active && (int)((u >> shift) & 0xFF) > bnd) {
                int slot = atomicAdd(&ctrl[2], 1);
                g_sel[b * KK + slot] = i;
            }
        }
        __syncthreads();
    }

    // Exact tie handling at the threshold key: smallest indices win (jax rule)
    if (tid == 0) ctrl[3] = 0;
    __syncthreads();
    uint32_t T = (uint32_t)ctrl[4];
    for (int i = tid; i < NN; i += nthr)
        if (keys[i] == T) eqidx[atomicAdd(&ctrl[3], 1)] = i;
    __syncthreads();
    int R = ctrl[1], en = ctrl[3];
    for (int j = tid; j < en; j += nthr) {
        int idx = eqidx[j], rank = 0;
        for (int t2 = 0; t2 < en; ++t2) rank += (eqidx[t2] < idx);
        if (rank < R) {
            int slot = atomicAdd(&ctrl[2], 1);
            g_sel[b * KK + slot] = idx;
        }
    }
}

// ---------------------------------------------------------------------------
// 3) Gather selected rows + convert fp16 -> g_a
// ---------------------------------------------------------------------------
__global__ void gather_h_kernel(const float* __restrict__ x) {
    int m = blockIdx.x;
    int c = threadIdx.x;
    int tok = g_sel[m];
    size_t src = ((size_t)(m >> 11) * NN + tok) * DD + c * 4;
    float4 v = *reinterpret_cast<const float4*>(x + src);
    __half2 h0 = __floats2half2_rn(v.x, v.y);
    __half2 h1 = __floats2half2_rn(v.z, v.w);
    uint2 pk;
    pk.x = *reinterpret_cast<uint32_t*>(&h0);
    pk.y = *reinterpret_cast<uint32_t*>(&h1);
    *reinterpret_cast<uint2*>(g_a + (size_t)m * DD + c * 4) = pk;
}

// ---------------------------------------------------------------------------
// fp16 mma.sync GEMM (unchanged from R10 — at the legacy-HMMA rate floor):
// CTA 128x128, 256 thr (8 warps 4Mx2N, warp 32x64), lb(256,2) -> 2 CTAs/SM.
//   MODE 0: ffn1  A=g_a (K=1024), B=g_w1t  ->  g_h = h(gelu(C + b1))
//   MODE 1: ffn2  A=g_h (K=4096), B=g_w2t  ->  out[sel] = x[sel] + C + b2
// BK=64, 3-stage cp.async pipeline, ONE __syncthreads per K-iter.
// Row pitch 144B keeps ldmatrix phases conflict-free.
// ---------------------------------------------------------------------------
#define HPITCH_B 144                               // bytes per row (72 halves)
#define A_STG (128 * HPITCH_B)                     // 18432 B
#define B_STG (128 * HPITCH_B)                     // 18432 B
#define NSTG 3
#define GSMEM_SZ (NSTG * (A_STG + B_STG))          // 110592 B per CTA

__device__ __forceinline__ void ld_stage(uint32_t sb, int stage,
                                         const __half* __restrict__ A,
                                         const __half* __restrict__ Bw,
                                         int Kdim, int mt, int nt, int k0, int tid) {
    uint32_t abase = sb + stage * A_STG;
    uint32_t bbase = sb + NSTG * A_STG + stage * B_STG;
#pragma unroll
    for (int i = 0; i < 4; ++i) {
        int lin = i * 256 + tid;
        int row = lin >> 3, ch = lin & 7;
        CP_ASYNC16(abase + row * HPITCH_B + ch * 16,
                   A + (size_t)(mt * 128 + row) * Kdim + k0 + ch * 8);
    }
#pragma unroll
    for (int i = 0; i < 4; ++i) {
        int lin = i * 256 + tid;
        int row = lin >> 3, ch = lin & 7;
        CP_ASYNC16(bbase + row * HPITCH_B + ch * 16,
                   Bw + (size_t)(nt * 128 + row) * Kdim + k0 + ch * 8);
    }
}

template <int MODE>
__global__ __launch_bounds__(256, 2)
void mma_gemm(const float* __restrict__ bias,
              const float* __restrict__ xin,
              float* __restrict__ outp) {
    extern __shared__ uint32_t smw[];
    const __half* A    = (MODE == 0) ? g_a   : g_h;
    const __half* Bw   = (MODE == 0) ? g_w1t : g_w2t;
    const int     Kdim = (MODE == 0) ? DD : DFFN;
    const int     KT   = Kdim / 64;

    int tid = threadIdx.x, lane = tid & 31, wid = tid >> 5;
    int wm = wid >> 1, wn = wid & 1;               // warp tile: rows wm*32, cols wn*64
    int mt = blockIdx.y, nt = blockIdx.x;
    uint32_t sb = smem_u32(smw);

    int lrow = ((lane >> 3) & 1) * 8 + (lane & 7);
    int koff = (lane >= 16) ? 16 : 0;
    uint32_t a_off[2], b_off[4];
#pragma unroll
    for (int mi = 0; mi < 2; ++mi)
        a_off[mi] = (wm * 32 + mi * 16 + lrow) * HPITCH_B + koff;
#pragma unroll
    for (int p = 0; p < 4; ++p)
        b_off[p] = (wn * 64 + p * 16 + lrow) * HPITCH_B + koff;

    float acc[2][8][4];
#pragma unroll
    for (int mi = 0; mi < 2; ++mi)
#pragma unroll
        for (int ni = 0; ni < 8; ++ni)
#pragma unroll
            for (int q = 0; q < 4; ++q) acc[mi][ni][q] = 0.0f;

    ld_stage(sb, 0, A, Bw, Kdim, mt, nt, 0, tid);
    CP_COMMIT();
    ld_stage(sb, 1, A, Bw, Kdim, mt, nt, 64, tid);
    CP_COMMIT();

    int stage = 0;
    for (int k = 0; k < KT; ++k) {
        CP_WAIT1();
        __syncthreads();

        int pstage = stage + 2 >= NSTG ? stage + 2 - NSTG : stage + 2;
        if (k + 2 < KT)
            ld_stage(sb, pstage, A, Bw, Kdim, mt, nt, (k + 2) * 64, tid);
        CP_COMMIT();

        uint32_t As_addr = sb + stage * A_STG;
        uint32_t Bs_addr = sb + NSTG * A_STG + stage * B_STG;
#pragma unroll
        for (int ks = 0; ks < 4; ++ks) {           // 4 x K=16
            uint32_t a[2][4];
#pragma unroll
            for (int mi = 0; mi < 2; ++mi)
                LDSM_X4(a[mi][0], a[mi][1], a[mi][2], a[mi][3],
                        As_addr + a_off[mi] + ks * 32);
#pragma unroll
            for (int p = 0; p < 4; ++p) {
                uint32_t b0, b1, b2, b3;           // (ni0.k0, ni1.k0, ni0.k8, ni1.k8)
                LDSM_X4(b0, b1, b2, b3, Bs_addr + b_off[p] + ks * 32);
#pragma unroll
                for (int mi = 0; mi < 2; ++mi) {
                    MMA_F16(acc[mi][2 * p + 0], a[mi], b0, b2);
                    MMA_F16(acc[mi][2 * p + 1], a[mi], b1, b3);
                }
            }
        }
        stage = stage + 1 == NSTG ? 0 : stage + 1;
    }

    // ---------------- Epilogue ----------------
    int r = lane >> 2, c = lane & 3;
    if (MODE == 0) {
#pragma unroll
        for (int mi = 0; mi < 2; ++mi) {
#pragma unroll
            for (int half = 0; half < 2; ++half) {
                int m = mt * 128 + wm * 32 + mi * 16 + half * 8 + r;
                __half* hrow = g_h + (size_t)m * DFFN;
#pragma unroll
                for (int ni = 0; ni < 8; ++ni) {
                    int n = nt * 128 + wn * 64 + ni * 8 + c * 2;
                    float v0 = gelu_fast(acc[mi][ni][half * 2 + 0] + bias[n]);
                    float v1 = gelu_fast(acc[mi][ni][half * 2 + 1] + bias[n + 1]);
                    __half2 hv = __floats2half2_rn(v0, v1);
                    *reinterpret_cast<__half2*>(hrow + n) = hv;
                }
            }
        }
    } else {
#pragma unroll
        for (int mi = 0; mi < 2; ++mi) {
#pragma unroll
            for (int half = 0; half < 2; ++half) {
                int m = mt * 128 + wm * 32 + mi * 16 + half * 8 + r;
                int tok = g_sel[m];
                size_t base = ((size_t)(m >> 11) * NN + tok) * DD;
#pragma unroll
                for (int ni = 0; ni < 8; ++ni) {
                    int n = nt * 128 + wn * 64 + ni * 8 + c * 2;
                    float2 xv = *reinterpret_cast<const float2*>(xin + base + n);
                    float2 w;
                    w.x = xv.x + acc[mi][ni][half * 2 + 0] + bias[n];
                    w.y = xv.y + acc[mi][ni][half * 2 + 1] + bias[n + 1];
                    *reinterpret_cast<float2*>(outp + base + n) = w;
                }
            }
        }
    }
}

// ---------------------------------------------------------------------------
// Launch: x, gate_w, w1, b1, w2, b2, k
// ---------------------------------------------------------------------------
extern "C" void kernel_launch(void* const* d_in, const int* in_sizes, int n_in,
                              void* d_out, int out_size) {
    const float* x  = (const float*)d_in[0];
    const float* gw = (const float*)d_in[1];
    const float* w1 = (const float*)d_in[2];
    const float* b1 = (const float*)d_in[3];
    const float* w2 = (const float*)d_in[4];
    const float* b2 = (const float*)d_in[5];
    float* out = (float*)d_out;

    cudaFuncSetAttribute(mma_gemm<0>, cudaFuncAttributeMaxDynamicSharedMemorySize, GSMEM_SZ);
    cudaFuncSetAttribute(mma_gemm<1>, cudaFuncAttributeMaxDynamicSharedMemorySize, GSMEM_SZ);

    // 1) scores + out=x copy (reads x once for both)
    scores_copy_kernel<<<(BB * NN) / 8, 256>>>(x, gw, out);
    // 2) topk (4 CTAs) || w1^T || w2^T — concurrent in one launch
    mid_kernel<<<4 + 1024 + 1024, 1024, MID_SMEM>>>(w1, w2);
    // 3) gather selected rows -> fp16 A
    gather_h_kernel<<<MM, 256>>>(x);
    // 4) GEMM1: g_a[8192,1024] @ w1 -> g_h[8192,4096]  (gelu fused, fp16 out)
    mma_gemm<0><<<dim3(DFFN / 128, MM / 128), 256, GSMEM_SZ>>>(b1, nullptr, nullptr);
    // 5) GEMM2: g_h @ w2 + residual -> scattered into out
    mma_gemm<1><<<dim3(DD / 128, MM / 128), 256, GSMEM_SZ>>>(b2, x, out);
}

// round 15
// speedup vs baseline: 1.1264x; 1.0290x over previous
#include <cuda_runtime.h>
#include <cuda_fp16.h>
#include <cstdint>
#include <math.h>

// Problem constants (MoDRouter_48387101556956: fixed shapes)
#define BB   4
#define NN   4096
#define DD   1024
#define DFFN 4096
#define KK   2048
#define MM   (BB * KK)   // 8192 selected tokens total

// GEMM2 mixed split-K: 512 tiles = 136 whole + 376 split(x2) -> 888 = 3*296 CTAs
#define N_TILES2   512
#define N_WHOLE    136
#define N_SPLIT    376

// ---------------------------------------------------------------------------
// Device scratch
// ---------------------------------------------------------------------------
__device__ float  g_scores[BB * NN];
__device__ int    g_sel[MM];                       // selected token idx per (b,j)
__device__ int    g_unsel[MM];                     // complement token idx per (b,j)
__device__ __half g_a[(size_t)MM * DD];            // gathered fp16 A (16 MB)
__device__ __half g_w1t[(size_t)DFFN * DD];        // w1^T (n-major, K contig), fp16
__device__ __half g_w2t[(size_t)DD * DFFN];        // w2^T (n-major, K contig), fp16
__device__ __half g_h[(size_t)MM * DFFN];          // gelu(x@w1+b1), fp16 (64 MB)
__device__ float  g_part[(size_t)N_SPLIT * 2 * 128 * 128];  // split-K partials (49 MB)
__device__ int    g_cnt[N_SPLIT];                  // split-K arrival tickets

// ---------------------------------------------------------------------------
// Helpers
// ---------------------------------------------------------------------------
__device__ __forceinline__ uint32_t smem_u32(const void* p) {
    uint32_t a;
    asm("{ .reg .u64 t; cvta.to.shared.u64 t, %1; cvt.u32.u64 %0, t; }" : "=r"(a) : "l"(p));
    return a;
}
// gelu-tanh with HW MUFU tanh (sm_75+): |err| <= ~2^-11, inside error budget
__device__ __forceinline__ float gelu_fast(float u) {
    float arg = 0.7978845608028654f * (u + 0.044715f * u * u * u);
    float t;
    asm("tanh.approx.f32 %0, %1;" : "=f"(t) : "f"(arg));
    return 0.5f * u * (1.0f + t);
}

#define CP_ASYNC16(dst, src) \
    asm volatile("cp.async.cg.shared.global [%0], [%1], 16;" :: "r"(dst), "l"(src) : "memory")
#define CP_COMMIT() asm volatile("cp.async.commit_group;" ::: "memory")
#define CP_WAIT1()  asm volatile("cp.async.wait_group 1;" ::: "memory")

// m16n8k16 row.col fp16 MMA, fp32 accumulate (base-ISA, legal on sm_103)
#define MMA_F16(c, a, b0, b1)                                                         \
    asm volatile("mma.sync.aligned.m16n8k16.row.col.f32.f16.f16.f32 "                 \
                 "{%0,%1,%2,%3}, {%4,%5,%6,%7}, {%8,%9}, {%0,%1,%2,%3};"              \
                 : "+f"((c)[0]), "+f"((c)[1]), "+f"((c)[2]), "+f"((c)[3])             \
                 : "r"((a)[0]), "r"((a)[1]), "r"((a)[2]), "r"((a)[3]), "r"(b0), "r"(b1))

// ldmatrix 4x m8n8 b16 (non-transposed)
#define LDSM_X4(r0, r1, r2, r3, addr)                                                 \
    asm volatile("ldmatrix.sync.aligned.m8n8.x4.shared.b16 {%0,%1,%2,%3}, [%4];"      \
                 : "=r"(r0), "=r"(r1), "=r"(r2), "=r"(r3) : "r"(addr))

// ---------------------------------------------------------------------------
// 1) Gate scores — one warp per row. Zeroes ALL split-K tickets each launch
//    (R12 bug: only zeroed tid<256 of 376 slots -> stale tickets on replay).
// ---------------------------------------------------------------------------
__global__ void scores_kernel(const float* __restrict__ x,
                              const float* __restrict__ gw) {
    if (blockIdx.x == 0)
        for (int i = threadIdx.x; i < N_SPLIT; i += blockDim.x) g_cnt[i] = 0;
    int gwarp = (blockIdx.x * blockDim.x + threadIdx.x) >> 5;
    int lane  = threadIdx.x & 31;
    if (gwarp >= BB * NN) return;
    const float4* xr = reinterpret_cast<const float4*>(x + (size_t)gwarp * DD);
    const float4* g4 = reinterpret_cast<const float4*>(gw);
    float s = 0.0f;
#pragma unroll
    for (int i = 0; i < DD / 4 / 32; ++i) {
        float4 a = xr[lane + i * 32];
        float4 b = g4[lane + i * 32];
        s += a.x * b.x + a.y * b.y + a.z * b.z + a.w * b.w;
    }
#pragma unroll
    for (int o = 16; o; o >>= 1) s += __shfl_xor_sync(0xFFFFFFFFu, s, o);
    if (lane == 0) g_scores[gwarp] = s;
}

// ---------------------------------------------------------------------------
// 2) MID kernel: CTAs 0-3 run per-batch exact top-K (radix select) AND build
//    the complement list; CTAs 4..2051 transpose w1/w2 to fp16 K-major.
// ---------------------------------------------------------------------------
#define MID_SMEM 33824   // keys 16K | eqidx/flags 16K | hist 1K | ctrl 32B

__global__ void mid_kernel(const float* __restrict__ w1,
                           const float* __restrict__ w2) {
    extern __shared__ char sh[];
    int bid = blockIdx.x, tid = threadIdx.x, nthr = blockDim.x;

    if (bid >= 4) {
        // ---- transpose path: 4 subtiles of 32x32 per CTA ----
        float (*t)[32][33] = reinterpret_cast<float (*)[32][33]>(sh);
        int sub  = tid >> 8;
        int stid = tid & 255;
        int tx = stid & 31, ty = stid >> 5;
        const float* src; __half* dst; int R, C, bx, by;
        if (bid < 4 + 1024) {
            int r = (bid - 4) * 4 + sub;
            src = w1; dst = g_w1t; R = DD; C = DFFN;
            bx = (r & 127) * 32; by = (r >> 7) * 32;
        } else {
            int r = (bid - 4 - 1024) * 4 + sub;
            src = w2; dst = g_w2t; R = DFFN; C = DD;
            bx = (r & 31) * 32; by = (r >> 5) * 32;
        }
#pragma unroll
        for (int i = 0; i < 32; i += 8)
            t[sub][ty + i][tx] = src[(size_t)(by + ty + i) * C + bx + tx];
        __syncthreads();
#pragma unroll
        for (int i = 0; i < 32; i += 8)
            dst[(size_t)(bx + ty + i) * R + by + tx] = __float2half_rn(t[sub][tx][ty + i]);
        return;
    }

    // ---- top-K path (CTAs 0-3, one batch each) ----
    uint32_t* keys  = reinterpret_cast<uint32_t*>(sh);
    int*      eqidx = reinterpret_cast<int*>(sh + 16384);
    int*      hist  = reinterpret_cast<int*>(sh + 32768);
    int*      ctrl  = reinterpret_cast<int*>(sh + 33792);
    int b = bid;

    for (int i = tid; i < NN; i += nthr) {
        uint32_t u = __float_as_uint(g_scores[b * NN + i]);
        u = (u & 0x80000000u) ? ~u : (u | 0x80000000u);   // monotone map
        keys[i] = u;
    }
    if (tid == 0) { ctrl[1] = KK; ctrl[2] = 0; ctrl[4] = 0; }
    __syncthreads();

    for (int byte = 3; byte >= 0; --byte) {
        if (tid < 256) hist[tid] = 0;
        __syncthreads();
        int shift = byte * 8;
        uint32_t pfx = (uint32_t)ctrl[4];
        for (int i = tid; i < NN; i += nthr) {
            uint32_t u = keys[i];
            bool active = (byte == 3) || ((u >> (shift + 8)) == pfx);
            if (active) atomicAdd(&hist[(u >> shift) & 0xFF], 1);
        }
        __syncthreads();
        if (tid == 0) {
            int R = ctrl[1], cum = 0, v = 255;
            for (; v > 0; --v) {
                if (cum + hist[v] >= R) break;
                cum += hist[v];
            }
            ctrl[0] = v;
            ctrl[1] = R - cum;
            ctrl[4] = (int)((pfx << 8) | (uint32_t)v);
        }
        __syncthreads();
        int bnd = ctrl[0];
        for (int i = tid; i < NN; i += nthr) {
            uint32_t u = keys[i];
            bool active = (byte == 3) || ((u >> (shift + 8)) == pfx);
            if (active && (int)((u >> shift) & 0xFF) > bnd) {
                int slot = atomicAdd(&ctrl[2], 1);
                g_sel[b * KK + slot] = i;
            }
        }
        __syncthreads();
    }

    // Exact tie handling at the threshold key: smallest indices win (jax rule)
    if (tid == 0) ctrl[3] = 0;
    __syncthreads();
    uint32_t T = (uint32_t)ctrl[4];
    for (int i = tid; i < NN; i += nthr)
        if (keys[i] == T) eqidx[atomicAdd(&ctrl[3], 1)] = i;
    __syncthreads();
    int R = ctrl[1], en = ctrl[3];
    for (int j = tid; j < en; j += nthr) {
        int idx = eqidx[j], rank = 0;
        for (int t2 = 0; t2 < en; ++t2) rank += (eqidx[t2] < idx);
        if (rank < R) {
            int slot = atomicAdd(&ctrl[2], 1);
            g_sel[b * KK + slot] = idx;
        }
    }

    // ---- complement list: flags from g_sel (just written by THIS CTA) ----
    __syncthreads();
    int* flags = eqidx;                         // reuse 16KB as 4096 int flags
    for (int i = tid; i < NN; i += nthr) flags[i] = 0;
    if (tid == 0) ctrl[5] = 0;
    __syncthreads();
    for (int j = tid; j < KK; j += nthr) flags[g_sel[b * KK + j]] = 1;
    __syncthreads();
    for (int i = tid; i < NN; i += nthr)
        if (!flags[i]) {
            int slot = atomicAdd(&ctrl[5], 1);
            g_unsel[b * KK + slot] = i;
        }
}

// ---------------------------------------------------------------------------
// 3) Gather selected rows -> fp16 g_a  ||  copy non-selected rows x -> out
// ---------------------------------------------------------------------------
__global__ void gather_copy_kernel(const float* __restrict__ x,
                                   float* __restrict__ out) {
    int bid = blockIdx.x, c = threadIdx.x;
    if (bid < MM) {
        int tok = g_sel[bid];
        size_t src = ((size_t)(bid >> 11) * NN + tok) * DD + c * 4;
        float4 v = *reinterpret_cast<const float4*>(x + src);
        __half2 h0 = __floats2half2_rn(v.x, v.y);
        __half2 h1 = __floats2half2_rn(v.z, v.w);
        uint2 pk;
        pk.x = *reinterpret_cast<uint32_t*>(&h0);
        pk.y = *reinterpret_cast<uint32_t*>(&h1);
        *reinterpret_cast<uint2*>(g_a + (size_t)bid * DD + c * 4) = pk;
    } else {
        int m2 = bid - MM;
        int tok = g_unsel[m2];
        size_t base = ((size_t)(m2 >> 11) * NN + tok) * DD + c * 4;
        *reinterpret_cast<float4*>(out + base) =
            *reinterpret_cast<const float4*>(x + base);
    }
}

// ---------------------------------------------------------------------------
// fp16 mma.sync GEMM core (mainloop at the legacy-HMMA rate floor):
// CTA tile 128x128, 256 thr (8 warps 4Mx2N, warp 32x64), lb(256,2) -> 2/SM.
//   MODE 0: ffn1, 2D grid (32,64):  g_h = h(gelu(g_a @ w1t^T + b1))
//   MODE 1: ffn2, 1D grid 888, mixed split-K:
//     bid < N_WHOLE: whole-K tile -> out[sel] = x[sel] + C + b2
//     else: half-K tile -> partial to g_part; 2nd arriver combines+scatters
// ---------------------------------------------------------------------------
#define HPITCH_B 144                               // bytes per row (72 halves)
#define A_STG (128 * HPITCH_B)
#define B_STG (128 * HPITCH_B)
#define NSTG 3
#define GSMEM_SZ (NSTG * (A_STG + B_STG))          // 110592 B per CTA

__device__ __forceinline__ void ld_stage(uint32_t sb, int stage,
                                         const __half* __restrict__ A,
                                         const __half* __restrict__ Bw,
                                         int Kdim, int mt, int nt, int k0, int tid) {
    uint32_t abase = sb + stage * A_STG;
    uint32_t bbase = sb + NSTG * A_STG + stage * B_STG;
#pragma unroll
    for (int i = 0; i < 4; ++i) {
        int lin = i * 256 + tid;
        int row = lin >> 3, ch = lin & 7;
        CP_ASYNC16(abase + row * HPITCH_B + ch * 16,
                   A + (size_t)(mt * 128 + row) * Kdim + k0 + ch * 8);
    }
#pragma unroll
    for (int i = 0; i < 4; ++i) {
        int lin = i * 256 + tid;
        int row = lin >> 3, ch = lin & 7;
        CP_ASYNC16(bbase + row * HPITCH_B + ch * 16,
                   Bw + (size_t)(nt * 128 + row) * Kdim + k0 + ch * 8);
    }
}

template <int MODE>
__global__ __launch_bounds__(256, 2)
void mma_gemm(const float* __restrict__ bias,
              const float* __restrict__ xin,
              float* __restrict__ outp) {
    extern __shared__ uint32_t smw[];
    __shared__ int sh_ticket;
    const __half* A    = (MODE == 0) ? g_a   : g_h;
    const __half* Bw   = (MODE == 0) ? g_w1t : g_w2t;
    const int     Kdim = (MODE == 0) ? DD : DFFN;

    int tid = threadIdx.x, lane = tid & 31, wid = tid >> 5;
    int wm = wid >> 1, wn = wid & 1;               // warp tile: rows wm*32, cols wn*64

    // tile decode
    int mt, nt, k0base, KT, half;                  // half = -1 for whole-K
    if (MODE == 0) {
        mt = blockIdx.y; nt = blockIdx.x; k0base = 0; KT = Kdim / 64; half = -1;
    } else {
        int bid = blockIdx.x, tile;
        if (bid < N_WHOLE) { tile = bid; k0base = 0; KT = 64; half = -1; }
        else {
            int i = bid - N_WHOLE;
            tile = N_WHOLE + (i >> 1); half = i & 1;
            k0base = half * 2048; KT = 32;
        }
        mt = tile >> 3; nt = tile & 7;
    }
    uint32_t sb = smem_u32(smw);

    int lrow = ((lane >> 3) & 1) * 8 + (lane & 7);
    int koff = (lane >= 16) ? 16 : 0;
    uint32_t a_off[2], b_off[4];
#pragma unroll
    for (int mi = 0; mi < 2; ++mi)
        a_off[mi] = (wm * 32 + mi * 16 + lrow) * HPITCH_B + koff;
#pragma unroll
    for (int p = 0; p < 4; ++p)
        b_off[p] = (wn * 64 + p * 16 + lrow) * HPITCH_B + koff;

    float acc[2][8][4];
#pragma unroll
    for (int mi = 0; mi < 2; ++mi)
#pragma unroll
        for (int ni = 0; ni < 8; ++ni)
#pragma unroll
            for (int q = 0; q < 4; ++q) acc[mi][ni][q] = 0.0f;

    ld_stage(sb, 0, A, Bw, Kdim, mt, nt, k0base, tid);
    CP_COMMIT();
    ld_stage(sb, 1, A, Bw, Kdim, mt, nt, k0base + 64, tid);
    CP_COMMIT();

    int stage = 0;
    for (int k = 0; k < KT; ++k) {
        CP_WAIT1();
        __syncthreads();

        int pstage = stage + 2 >= NSTG ? stage + 2 - NSTG : stage + 2;
        if (k + 2 < KT)
            ld_stage(sb, pstage, A, Bw, Kdim, mt, nt, k0base + (k + 2) * 64, tid);
        CP_COMMIT();

        uint32_t As_addr = sb + stage * A_STG;
        uint32_t Bs_addr = sb + NSTG * A_STG + stage * B_STG;
#pragma unroll
        for (int ks = 0; ks < 4; ++ks) {           // 4 x K=16
            uint32_t a[2][4];
#pragma unroll
            for (int mi = 0; mi < 2; ++mi)
                LDSM_X4(a[mi][0], a[mi][1], a[mi][2], a[mi][3],
                        As_addr + a_off[mi] + ks * 32);
#pragma unroll
            for (int p = 0; p < 4; ++p) {
                uint32_t b0, b1, b2, b3;
                LDSM_X4(b0, b1, b2, b3, Bs_addr + b_off[p] + ks * 32);
#pragma unroll
                for (int mi = 0; mi < 2; ++mi) {
                    MMA_F16(acc[mi][2 * p + 0], a[mi], b0, b2);
                    MMA_F16(acc[mi][2 * p + 1], a[mi], b1, b3);
                }
            }
        }
        stage = stage + 1 == NSTG ? 0 : stage + 1;
    }

    // ---------------- Epilogue ----------------
    int r = lane >> 2, c = lane & 3;
    if (MODE == 0) {
#pragma unroll
        for (int mi = 0; mi < 2; ++mi) {
#pragma unroll
            for (int hh = 0; hh < 2; ++hh) {
                int m = mt * 128 + wm * 32 + mi * 16 + hh * 8 + r;
                __half* hrow = g_h + (size_t)m * DFFN;
#pragma unroll
                for (int ni = 0; ni < 8; ++ni) {
                    int n = nt * 128 + wn * 64 + ni * 8 + c * 2;
                    float v0 = gelu_fast(acc[mi][ni][hh * 2 + 0] + bias[n]);
                    float v1 = gelu_fast(acc[mi][ni][hh * 2 + 1] + bias[n + 1]);
                    __half2 hv = __floats2half2_rn(v0, v1);
                    *reinterpret_cast<__half2*>(hrow + n) = hv;
                }
            }
        }
    } else if (half < 0) {
        // whole-K tile: residual + scatter
#pragma unroll
        for (int mi = 0; mi < 2; ++mi) {
#pragma unroll
            for (int hh = 0; hh < 2; ++hh) {
                int m = mt * 128 + wm * 32 + mi * 16 + hh * 8 + r;
                int tok = g_sel[m];
                size_t base = ((size_t)(m >> 11) * NN + tok) * DD;
#pragma unroll
                for (int ni = 0; ni < 8; ++ni) {
                    int n = nt * 128 + wn * 64 + ni * 8 + c * 2;
                    float2 xv = *reinterpret_cast<const float2*>(xin + base + n);
                    float2 w;
                    w.x = xv.x + acc[mi][ni][hh * 2 + 0] + bias[n];
                    w.y = xv.y + acc[mi][ni][hh * 2 + 1] + bias[n + 1];
                    *reinterpret_cast<float2*>(outp + base + n) = w;
                }
            }
        }
    } else {
        // split-K half: write partial, second arriver combines + scatters
        int sidx = (mt * 8 + nt) - N_WHOLE;        // 0..N_SPLIT-1
        float* slot = g_part + ((size_t)sidx * 2 + half) * 16384;
#pragma unroll
        for (int mi = 0; mi < 2; ++mi)
#pragma unroll
            for (int hh = 0; hh < 2; ++hh) {
                int ml = wm * 32 + mi * 16 + hh * 8 + r;
#pragma unroll
                for (int ni = 0; ni < 8; ++ni) {
                    int nl = wn * 64 + ni * 8 + c * 2;
                    float2 v = make_float2(acc[mi][ni][hh * 2], acc[mi][ni][hh * 2 + 1]);
                    *reinterpret_cast<float2*>(slot + ml * 128 + nl) = v;
                }
            }
        __threadfence();
        __syncthreads();
        if (tid == 0) sh_ticket = atomicAdd(&g_cnt[sidx], 1);
        __syncthreads();
        if (sh_ticket == 1) {
            __threadfence();
            const float* oslot = g_part + ((size_t)sidx * 2 + (half ^ 1)) * 16384;
#pragma unroll
            for (int mi = 0; mi < 2; ++mi)
#pragma unroll
                for (int hh = 0; hh < 2; ++hh) {
                    int ml = wm * 32 + mi * 16 + hh * 8 + r;
                    int m = mt * 128 + ml;
                    int tok = g_sel[m];
                    size_t base = ((size_t)(m >> 11) * NN + tok) * DD;
#pragma unroll
                    for (int ni = 0; ni < 8; ++ni) {
                        int nl = wn * 64 + ni * 8 + c * 2;
                        int n = nt * 128 + nl;
                        float2 p = __ldcg(reinterpret_cast<const float2*>(oslot + ml * 128 + nl));
                        float2 xv = *reinterpret_cast<const float2*>(xin + base + n);
                        float2 w;
                        w.x = xv.x + (p.x + acc[mi][ni][hh * 2 + 0]) + bias[n];
                        w.y = xv.y + (p.y + acc[mi][ni][hh * 2 + 1]) + bias[n + 1];
                        *reinterpret_cast<float2*>(outp + base + n) = w;
                    }
                }
        }
    }
}

// ---------------------------------------------------------------------------
// Launch: x, gate_w, w1, b1, w2, b2, k
// ---------------------------------------------------------------------------
extern "C" void kernel_launch(void* const* d_in, const int* in_sizes, int n_in,
                              void* d_out, int out_size) {
    const float* x  = (const float*)d_in[0];
    const float* gw = (const float*)d_in[1];
    const float* w1 = (const float*)d_in[2];
    const float* b1 = (const float*)d_in[3];
    const float* w2 = (const float*)d_in[4];
    const float* b2 = (const float*)d_in[5];
    float* out = (float*)d_out;

    cudaFuncSetAttribute(mma_gemm<0>, cudaFuncAttributeMaxDynamicSharedMemorySize, GSMEM_SZ);
    cudaFuncSetAttribute(mma_gemm<1>, cudaFuncAttributeMaxDynamicSharedMemorySize, GSMEM_SZ);

    // 1) gate scores (+ zero ALL split-K tickets — replay-safe)
    scores_kernel<<<(BB * NN) / 8, 256>>>(x, gw);
    // 2) topk + complement (4 CTAs) || w1^T || w2^T — one launch
    mid_kernel<<<4 + 1024 + 1024, 1024, MID_SMEM>>>(w1, w2);
    // 3) gather selected -> fp16 A || copy non-selected x -> out
    gather_copy_kernel<<<2 * MM, 256>>>(x, out);
    // 4) GEMM1: g_a[8192,1024] @ w1 -> g_h[8192,4096]  (gelu fused, fp16 out)
    mma_gemm<0><<<dim3(DFFN / 128, MM / 128), 256, GSMEM_SZ>>>(b1, nullptr, nullptr);
    // 5) GEMM2 mixed split-K: g_h @ w2 + residual -> scattered into out
    mma_gemm<1><<<N_WHOLE + 2 * N_SPLIT, 256, GSMEM_SZ>>>(b2, x, out);
}